// round 10
// baseline (speedup 1.0000x reference)
#include <cuda_runtime.h>
#include <cuda_fp16.h>
#include <math.h>
#include <cstdint>
#include <string.h>

// ---------------- problem constants ----------------
#define TOK   2048
#define DDIM  1024
#define FDIM  4096
#define NEXP  8
#define FSH   512
#define TOPK  2
#define ROWCAP (NEXP*TOK)
#define NROWS  (ROWCAP + TOK)
#define NSLOT  9          // 8 routed + merged shared (slot 8)

// ---------------- scratch (device globals) ----------------
__device__ int   g_cnt[NEXP];
__device__ int   g_tok[ROWCAP];
__device__ int   g_rowof[TOK * TOPK];
__device__ float g_gw[TOK * TOPK];
__device__ __half g_x[TOK * DDIM];
// W' : per slot 2*FDIM rows (g/u interleaved in 32-row blocks), K-major [r'][D]
__device__ __half g_wgT[(size_t)NSLOT * 2 * FDIM * DDIM];
__device__ __half g_w2T[(size_t)NSLOT * DDIM * FDIM];   // [slot][D][F] fp16
__device__ __half g_h[(size_t)NROWS * FDIM];
__device__ float g_orow[(size_t)NROWS * DDIM];

// ---------------- helpers ----------------
__device__ __forceinline__ uint32_t smem_u32(const void* p) {
    uint32_t a;
    asm("{ .reg .u64 t; cvta.to.shared.u64 t, %1; cvt.u32.u64 %0, t; }" : "=r"(a) : "l"(p));
    return a;
}
__device__ __forceinline__ void ldsm4(uint32_t* r, uint32_t a) {
    asm volatile("ldmatrix.sync.aligned.m8n8.x4.shared.b16 {%0,%1,%2,%3}, [%4];"
                 : "=r"(r[0]), "=r"(r[1]), "=r"(r[2]), "=r"(r[3]) : "r"(a));
}
__device__ __forceinline__ void mma_f16(float* c, const uint32_t* a, const uint32_t* b) {
    asm volatile(
        "mma.sync.aligned.m16n8k16.row.col.f32.f16.f16.f32 "
        "{%0,%1,%2,%3},{%4,%5,%6,%7},{%8,%9},{%0,%1,%2,%3};"
        : "+f"(c[0]), "+f"(c[1]), "+f"(c[2]), "+f"(c[3])
        : "r"(a[0]), "r"(a[1]), "r"(a[2]), "r"(a[3]), "r"(b[0]), "r"(b[1]));
}
#define CP16(dst, src) \
    asm volatile("cp.async.cg.shared.global [%0], [%1], 16;" :: "r"(dst), "l"(src))
#define CPCOMMIT() asm volatile("cp.async.commit_group;" ::: "memory")
#define CPWAIT0()  asm volatile("cp.async.wait_group 0;" ::: "memory")

__device__ __forceinline__ unsigned pk2h(__half a, __half b) {
    __half2 t = __halves2half2(a, b);
    unsigned r; memcpy(&r, &t, 4); return r;
}

// ============================ reset / gate ===============================
__global__ void k_reset() {
    if (threadIdx.x < NEXP) g_cnt[threadIdx.x] = 0;
}

__global__ void k_gate(const float* __restrict__ x, const float* __restrict__ gateW) {
    int gwarp = (blockIdx.x * blockDim.x + threadIdx.x) >> 5;
    int lane  = threadIdx.x & 31;
    if (gwarp >= TOK) return;
    const float* xr = x + (size_t)gwarp * DDIM;
    float xv[32];
#pragma unroll
    for (int i = 0; i < 32; i++) xv[i] = xr[lane + 32 * i];
    float logit[NEXP];
#pragma unroll
    for (int e = 0; e < NEXP; e++) {
        const float* wr = gateW + e * DDIM;
        float acc = 0.f;
#pragma unroll
        for (int i = 0; i < 32; i++) acc += xv[i] * wr[lane + 32 * i];
#pragma unroll
        for (int o = 16; o > 0; o >>= 1) acc += __shfl_xor_sync(0xffffffffu, acc, o);
        logit[e] = acc;
    }
    if (lane == 0) {
        float m = logit[0];
#pragma unroll
        for (int e = 1; e < NEXP; e++) m = fmaxf(m, logit[e]);
        float p[NEXP], den = 0.f;
#pragma unroll
        for (int e = 0; e < NEXP; e++) { p[e] = expf(logit[e] - m); den += p[e]; }
        int i1 = 0;
#pragma unroll
        for (int e = 1; e < NEXP; e++) if (p[e] > p[i1]) i1 = e;
        int i2 = (i1 == 0) ? 1 : 0;
#pragma unroll
        for (int e = 0; e < NEXP; e++) if (e != i2 && e != i1 && p[e] > p[i2]) i2 = e;
        int pos1 = atomicAdd(&g_cnt[i1], 1);
        int r1 = i1 * TOK + pos1;
        g_tok[r1] = gwarp;
        g_rowof[2 * gwarp + 0] = r1;
        g_gw[2 * gwarp + 0] = p[i1] / den;
        int pos2 = atomicAdd(&g_cnt[i2], 1);
        int r2 = i2 * TOK + pos2;
        g_tok[r2] = gwarp;
        g_rowof[2 * gwarp + 1] = r2;
        g_gw[2 * gwarp + 1] = p[i2] / den;
    }
}

// ===================== weight transpose (fp16) ===========================
__global__ __launch_bounds__(256) void k_transplit(
    const float* __restrict__ src, int dst_id, size_t extra,
    int R, int C, size_t sstride, size_t dstride, int goff)
{
    __shared__ float tile[32][33];
    __half* dst = (dst_id == 0) ? g_wgT : g_w2T;
    dst += extra;

    int z = blockIdx.z;
    const float* s = src + (size_t)z * sstride;
    size_t dbase = (size_t)z * dstride;
    int c0 = blockIdx.x * 32, r0 = blockIdx.y * 32;
    int tx = threadIdx.x & 31, ty = threadIdx.x >> 5;
#pragma unroll
    for (int i = 0; i < 4; i++)
        tile[ty + 8 * i][tx] = s[(size_t)(r0 + ty + 8 * i) * C + c0 + tx];
    __syncthreads();
#pragma unroll
    for (int i = 0; i < 4; i++) {
        float v = tile[tx][ty + 8 * i];
        int r = c0 + ty + 8 * i;              // output row (F-index)
        int rr = (goff >= 0) ? (((r >> 5) << 6) + goff + (r & 31)) : r;
        size_t o = dbase + (size_t)rr * R + r0 + tx;
        dst[o] = __float2half_rn(v);
    }
}

__global__ void k_xsplit(const float* __restrict__ x) {
    int i = blockIdx.x * blockDim.x + threadIdx.x;
    g_x[i] = __float2half_rn(x[i]);
}

// ============================ GEMM tiles ================================
#define LDT 72          // smem row stride (144B): 16B-aligned, 4-bank row stagger
#define NSTG 2
#define BK 64

// ---- GEMM1: 128(M) x 128(W'-rows) x 64, warps 4(M) x 2(N) ----
#define G1_A    0
#define G1_B    (128 * LDT)               // 9216 elems
#define G1_STG  (256 * LDT)               // 18432 elems / stage
#define G1_STGB (G1_STG * 2)              // 36864 B
#define G1_SMEM (NSTG * G1_STGB + 512)

__global__ __launch_bounds__(256, 2) void k_gemm1() {
    const int z   = blockIdx.z;
    const int m0  = blockIdx.y * 128;
    const int n0p = blockIdx.x * 128;     // W' row base
    const int M   = (z < NEXP) ? g_cnt[z] : TOK;
    if (m0 >= M) return;
    const size_t rowbase = (z < NEXP) ? ((size_t)z * TOK + m0) : ((size_t)ROWCAP + m0);

    extern __shared__ __align__(16) char sm[];
    int* stok = (int*)(sm + NSTG * G1_STGB);
    const int tid = threadIdx.x;
    if (tid < 128) {
        int r = m0 + tid; if (r > M - 1) r = M - 1;
        stok[tid] = (z < NEXP) ? g_tok[z * TOK + r] : r;
    }
    __syncthreads();

    const uint32_t sbu = smem_u32(sm);
    // staging: 2 threads per row; thread p covers elems p*32..p*32+31 (4 chunks of 8)
    const int ra = tid >> 1, pe = (tid & 1) * 32;
    const __half* sxp = g_x + (size_t)stok[ra] * DDIM + pe;
    const __half* sBp = g_wgT + ((size_t)z * 2 * FDIM + n0p + ra) * DDIM + pe;

    const uint32_t dA = (ra * LDT + pe) * 2;
    const uint32_t dB = (G1_B + ra * LDT + pe) * 2;

    const int lane = tid & 31, w = tid >> 5;
    const int wm = w >> 1, wn = w & 1;
    const int qr = lane >> 2, qc = lane & 3;
    const uint32_t aoff = ((wm * 32 + (lane & 15)) * LDT + (lane >> 4) * 8) * 2;
    const uint32_t boff = (G1_B + (wn * 64 + (lane & 7) + ((lane >> 4) & 1) * 8) * LDT
                           + ((lane >> 3) & 1) * 8) * 2;

    float acc[2][8][4] = {};

#define G1_LOAD(it) do { \
    const int k0 = (it) * BK; \
    const uint32_t db = sbu + ((it) & 1) * G1_STGB; \
    CP16(db + dA,      sxp + k0); \
    CP16(db + dA + 16, sxp + k0 + 8); \
    CP16(db + dA + 32, sxp + k0 + 16); \
    CP16(db + dA + 48, sxp + k0 + 24); \
    CP16(db + dB,      sBp + k0); \
    CP16(db + dB + 16, sBp + k0 + 8); \
    CP16(db + dB + 32, sBp + k0 + 16); \
    CP16(db + dB + 48, sBp + k0 + 24); \
    CPCOMMIT(); \
} while (0)

    G1_LOAD(0);

    const int NIT = DDIM / BK;   // 16
    for (int it = 0; it < NIT; it++) {
        CPWAIT0();
        __syncthreads();
        if (it + 1 < NIT) G1_LOAD(it + 1);
        const uint32_t stg = sbu + (it & 1) * G1_STGB;
#pragma unroll
        for (int ks = 0; ks < BK; ks += 16) {
            uint32_t ah[2][4];
#pragma unroll
            for (int mt = 0; mt < 2; mt++)
                ldsm4(ah[mt], stg + aoff + mt * (16 * LDT * 2) + ks * 2);
#pragma unroll
            for (int nh = 0; nh < 4; nh++) {
                uint32_t bb[4];
                ldsm4(bb, stg + boff + nh * (16 * LDT * 2) + ks * 2);
#pragma unroll
                for (int t = 0; t < 2; t++) {
                    const int nt = nh * 2 + t;
#pragma unroll
                    for (int mt = 0; mt < 2; mt++)
                        mma_f16(acc[mt][nt], ah[mt], bb + 2 * t);
                }
            }
        }
    }
#undef G1_LOAD

    // epilogue: GLU pairing in-register: g = acc[mt][nt], u = acc[mt][nt+4]
    const int fb = blockIdx.x * 64 + wn * 32;
#pragma unroll
    for (int mt = 0; mt < 2; mt++)
#pragma unroll
        for (int nt = 0; nt < 4; nt++) {
            const int R = wm * 32 + mt * 16 + qr;
            const int C = fb + nt * 8 + 2 * qc;
#pragma unroll
            for (int half = 0; half < 2; half++) {
                const int r = R + half * 8;
                float g0 = acc[mt][nt][2 * half],     u0 = acc[mt][nt + 4][2 * half];
                float g1 = acc[mt][nt][2 * half + 1], u1 = acc[mt][nt + 4][2 * half + 1];
                float o0 = g0 / (1.f + __expf(-g0)) * u0;
                float o1 = g1 / (1.f + __expf(-g1)) * u1;
                const size_t idx = (rowbase + r) * (size_t)FDIM + C;
                *(unsigned*)&g_h[idx] = pk2h(__float2half_rn(o0), __float2half_rn(o1));
            }
        }
}

// ---- GEMM2: 128 x 64 x 64, warps 4 x 2 over (32M x 32N) ----
#define G2_A    0
#define G2_B    (128 * LDT)
#define G2_STG  (192 * LDT)               // 13824 elems / stage
#define G2_STGB (G2_STG * 2)              // 27648 B
#define G2_SMEM (NSTG * G2_STGB)

__global__ __launch_bounds__(256, 2) void k_gemm2() {
    const int z  = blockIdx.z;
    const int m0 = blockIdx.y * 128;
    const int n0 = blockIdx.x * 64;
    const int M  = (z < NEXP) ? g_cnt[z] : TOK;
    if (m0 >= M) return;
    const size_t rowbase = (z < NEXP) ? ((size_t)z * TOK + m0) : ((size_t)ROWCAP + m0);

    extern __shared__ __align__(16) char sm[];
    const uint32_t sbu = smem_u32(sm);
    const int tid = threadIdx.x;
    // A: 2 threads/row, thread p covers elems p*32..p*32+31
    const int ra = tid >> 1, pe = (tid & 1) * 32;
    // B: 4 threads/row, thread q covers elems q*16..q*16+15
    const int rb = tid >> 2, qe = (tid & 3) * 16;

    const __half* sap = g_h + (rowbase + ra) * (size_t)FDIM + pe;
    const __half* sBp = g_w2T + ((size_t)z * DDIM + n0 + rb) * FDIM + qe;

    const uint32_t dA = (ra * LDT + pe) * 2;
    const uint32_t dB = (G2_B + rb * LDT + qe) * 2;

    const int lane = tid & 31, w = tid >> 5;
    const int wm = w >> 1, wn = w & 1;
    const int qr = lane >> 2, qc = lane & 3;
    const uint32_t aoff = ((wm * 32 + (lane & 15)) * LDT + (lane >> 4) * 8) * 2;
    const uint32_t boff = (G2_B + (wn * 32 + (lane & 7) + ((lane >> 4) & 1) * 8) * LDT
                           + ((lane >> 3) & 1) * 8) * 2;

    float acc[2][4][4] = {};

#define G2_LOAD(it) do { \
    const int k0 = (it) * BK; \
    const uint32_t db = sbu + ((it) & 1) * G2_STGB; \
    CP16(db + dA,      sap + k0); \
    CP16(db + dA + 16, sap + k0 + 8); \
    CP16(db + dA + 32, sap + k0 + 16); \
    CP16(db + dA + 48, sap + k0 + 24); \
    CP16(db + dB,      sBp + k0); \
    CP16(db + dB + 16, sBp + k0 + 8); \
    CPCOMMIT(); \
} while (0)

    G2_LOAD(0);

    const int NIT = FDIM / BK;   // 64
    for (int it = 0; it < NIT; it++) {
        CPWAIT0();
        __syncthreads();
        if (it + 1 < NIT) G2_LOAD(it + 1);
        const uint32_t stg = sbu + (it & 1) * G2_STGB;
#pragma unroll
        for (int ks = 0; ks < BK; ks += 16) {
            uint32_t ah[2][4];
#pragma unroll
            for (int mt = 0; mt < 2; mt++)
                ldsm4(ah[mt], stg + aoff + mt * (16 * LDT * 2) + ks * 2);
#pragma unroll
            for (int nh = 0; nh < 2; nh++) {
                uint32_t bb[4];
                ldsm4(bb, stg + boff + nh * (16 * LDT * 2) + ks * 2);
#pragma unroll
                for (int t = 0; t < 2; t++) {
                    const int nt = nh * 2 + t;
#pragma unroll
                    for (int mt = 0; mt < 2; mt++)
                        mma_f16(acc[mt][nt], ah[mt], bb + 2 * t);
                }
            }
        }
    }
#undef G2_LOAD

#pragma unroll
    for (int mt = 0; mt < 2; mt++)
#pragma unroll
        for (int nt = 0; nt < 4; nt++) {
            const int R = wm * 32 + mt * 16 + qr;
            const int C = wn * 32 + nt * 8 + 2 * qc;
#pragma unroll
            for (int half = 0; half < 2; half++) {
                const int r = R + half * 8;
                float2 o;
                o.x = acc[mt][nt][2 * half];
                o.y = acc[mt][nt][2 * half + 1];
                *(float2*)&g_orow[(rowbase + r) * (size_t)DDIM + n0 + C] = o;
            }
        }
}

// ============================ combine ===================================
__global__ void k_combine(float* __restrict__ out) {
    int idx = blockIdx.x * blockDim.x + threadIdx.x;
    if (idx >= TOK * DDIM) return;
    int t = idx >> 10;
    int d = idx & (DDIM - 1);
    float sh = g_orow[((size_t)ROWCAP + t) * DDIM + d];
    int   r0 = g_rowof[2 * t], r1 = g_rowof[2 * t + 1];
    float v = 0.0625f * sh
            + 0.5f * (g_gw[2 * t] * g_orow[(size_t)r0 * DDIM + d]
                    + g_gw[2 * t + 1] * g_orow[(size_t)r1 * DDIM + d]);
    out[idx] = v;
}

// ============================ launch ====================================
extern "C" void kernel_launch(void* const* d_in, const int* in_sizes, int n_in,
                              void* d_out, int out_size) {
    const float* x   = (const float*)d_in[0];
    const float* gW  = (const float*)d_in[1];
    const float* w1e = (const float*)d_in[2];
    const float* w3e = (const float*)d_in[3];
    const float* w2e = (const float*)d_in[4];
    const float* w1s = (const float*)d_in[5];
    const float* w3s = (const float*)d_in[6];
    const float* w2s = (const float*)d_in[7];
    float* out = (float*)d_out;

    cudaFuncSetAttribute(k_gemm1, cudaFuncAttributeMaxDynamicSharedMemorySize, G1_SMEM);
    cudaFuncSetAttribute(k_gemm2, cudaFuncAttributeMaxDynamicSharedMemorySize, G2_SMEM);

    k_reset<<<1, 32>>>();
    k_gate<<<TOK / 8, 256>>>(x, gW);
    k_xsplit<<<TOK * DDIM / 256, 256>>>(x);

    // routed: w1/w3 -> interleaved W' slots 0..7; w2 -> w2T slots 0..7
    k_transplit<<<dim3(FDIM / 32, DDIM / 32, NEXP), 256>>>(
        w1e, 0, 0, DDIM, FDIM, (size_t)DDIM * FDIM, (size_t)2 * FDIM * DDIM, 0);
    k_transplit<<<dim3(FDIM / 32, DDIM / 32, NEXP), 256>>>(
        w3e, 0, 0, DDIM, FDIM, (size_t)DDIM * FDIM, (size_t)2 * FDIM * DDIM, 32);
    k_transplit<<<dim3(DDIM / 32, FDIM / 32, NEXP), 256>>>(
        w2e, 1, 0, FDIM, DDIM, (size_t)FDIM * DDIM, (size_t)DDIM * FDIM, -1);
    // shared experts -> slot 8 (block-concatenated); per-z W' span = 1024 rows
    k_transplit<<<dim3(FSH / 32, DDIM / 32, NEXP), 256>>>(
        w1s, 0, (size_t)NEXP * 2 * FDIM * DDIM, DDIM, FSH, (size_t)DDIM * FSH,
        (size_t)1024 * DDIM, 0);
    k_transplit<<<dim3(FSH / 32, DDIM / 32, NEXP), 256>>>(
        w3s, 0, (size_t)NEXP * 2 * FDIM * DDIM, DDIM, FSH, (size_t)DDIM * FSH,
        (size_t)1024 * DDIM, 32);
    k_transplit<<<dim3(DDIM / 32, FDIM / 32, 1), 256>>>(
        w2s, 1, (size_t)NEXP * DDIM * FDIM, FDIM, DDIM, 0, 0, -1);

    k_gemm1<<<dim3(2 * FDIM / 128, TOK / 128, NSLOT), 256, G1_SMEM>>>();
    k_gemm2<<<dim3(DDIM / 64, TOK / 128, NSLOT), 256, G2_SMEM>>>();
    k_combine<<<(TOK * DDIM) / 256, 256>>>(out);
}

// round 14
// speedup vs baseline: 1.3370x; 1.3370x over previous
#include <cuda_runtime.h>
#include <cuda_fp16.h>
#include <math.h>
#include <cstdint>
#include <string.h>

// ---------------- problem constants ----------------
#define TOK   2048
#define DDIM  1024
#define FDIM  4096
#define NEXP  8
#define FSH   512
#define TOPK  2
#define ROWCAP (NEXP*TOK)
#define NROWS  (ROWCAP + TOK)
#define NSLOT  9          // 8 routed + merged shared (slot 8)

// ---------------- scratch (device globals) ----------------
__device__ int   g_cnt[NEXP];
__device__ int   g_tok[ROWCAP];
__device__ int   g_rowof[TOK * TOPK];
__device__ float g_gw[TOK * TOPK];
__device__ __half g_x[TOK * DDIM];
// W' : per slot 2*FDIM rows (g/u interleaved in 32-row blocks), K-major [r'][D]
__device__ __half g_wgT[(size_t)NSLOT * 2 * FDIM * DDIM];
__device__ __half g_w2T[(size_t)NSLOT * DDIM * FDIM];   // [slot][D][F] fp16
__device__ __half g_h[(size_t)NROWS * FDIM];
__device__ float g_orow[(size_t)NROWS * DDIM];

// ---------------- helpers ----------------
__device__ __forceinline__ uint32_t smem_u32(const void* p) {
    uint32_t a;
    asm("{ .reg .u64 t; cvta.to.shared.u64 t, %1; cvt.u32.u64 %0, t; }" : "=r"(a) : "l"(p));
    return a;
}
__device__ __forceinline__ void ldsm4(uint32_t* r, uint32_t a) {
    asm volatile("ldmatrix.sync.aligned.m8n8.x4.shared.b16 {%0,%1,%2,%3}, [%4];"
                 : "=r"(r[0]), "=r"(r[1]), "=r"(r[2]), "=r"(r[3]) : "r"(a));
}
__device__ __forceinline__ void mma_f16(float* c, const uint32_t* a, const uint32_t* b) {
    asm volatile(
        "mma.sync.aligned.m16n8k16.row.col.f32.f16.f16.f32 "
        "{%0,%1,%2,%3},{%4,%5,%6,%7},{%8,%9},{%0,%1,%2,%3};"
        : "+f"(c[0]), "+f"(c[1]), "+f"(c[2]), "+f"(c[3])
        : "r"(a[0]), "r"(a[1]), "r"(a[2]), "r"(a[3]), "r"(b[0]), "r"(b[1]));
}
#define CP16(dst, src) \
    asm volatile("cp.async.cg.shared.global [%0], [%1], 16;" :: "r"(dst), "l"(src))
#define CPCOMMIT() asm volatile("cp.async.commit_group;" ::: "memory")
#define CPWAIT2()  asm volatile("cp.async.wait_group 2;" ::: "memory")

__device__ __forceinline__ unsigned pk2h(__half a, __half b) {
    __half2 t = __halves2half2(a, b);
    unsigned r; memcpy(&r, &t, 4); return r;
}

// ============================ reset / gate ===============================
__global__ void k_reset() {
    if (threadIdx.x < NEXP) g_cnt[threadIdx.x] = 0;
}

__global__ void k_gate(const float* __restrict__ x, const float* __restrict__ gateW) {
    int gwarp = (blockIdx.x * blockDim.x + threadIdx.x) >> 5;
    int lane  = threadIdx.x & 31;
    if (gwarp >= TOK) return;
    const float* xr = x + (size_t)gwarp * DDIM;
    float xv[32];
#pragma unroll
    for (int i = 0; i < 32; i++) xv[i] = xr[lane + 32 * i];
    float logit[NEXP];
#pragma unroll
    for (int e = 0; e < NEXP; e++) {
        const float* wr = gateW + e * DDIM;
        float acc = 0.f;
#pragma unroll
        for (int i = 0; i < 32; i++) acc += xv[i] * wr[lane + 32 * i];
#pragma unroll
        for (int o = 16; o > 0; o >>= 1) acc += __shfl_xor_sync(0xffffffffu, acc, o);
        logit[e] = acc;
    }
    if (lane == 0) {
        float m = logit[0];
#pragma unroll
        for (int e = 1; e < NEXP; e++) m = fmaxf(m, logit[e]);
        float p[NEXP], den = 0.f;
#pragma unroll
        for (int e = 0; e < NEXP; e++) { p[e] = expf(logit[e] - m); den += p[e]; }
        int i1 = 0;
#pragma unroll
        for (int e = 1; e < NEXP; e++) if (p[e] > p[i1]) i1 = e;
        int i2 = (i1 == 0) ? 1 : 0;
#pragma unroll
        for (int e = 0; e < NEXP; e++) if (e != i2 && e != i1 && p[e] > p[i2]) i2 = e;
        int pos1 = atomicAdd(&g_cnt[i1], 1);
        int r1 = i1 * TOK + pos1;
        g_tok[r1] = gwarp;
        g_rowof[2 * gwarp + 0] = r1;
        g_gw[2 * gwarp + 0] = p[i1] / den;
        int pos2 = atomicAdd(&g_cnt[i2], 1);
        int r2 = i2 * TOK + pos2;
        g_tok[r2] = gwarp;
        g_rowof[2 * gwarp + 1] = r2;
        g_gw[2 * gwarp + 1] = p[i2] / den;
    }
}

// ===================== weight transpose (fp16) v2 (fixed) ================
// Source z-block: rows = K dim, cols = output-row dim. Tile: 64 source rows
// x 32 source cols. Writes 128B contiguous per output row via __half2.
// goff>=0 -> GLU 32-block interleave of output rows.
__global__ __launch_bounds__(256) void k_transplit(
    const float* __restrict__ src, int dst_id, size_t extra,
    int R, int C, size_t sstride, size_t dstride, int goff)
{
    __shared__ float tile[64][33];
    __half* dst = (dst_id == 0) ? g_wgT : g_w2T;
    dst += extra;

    int z = blockIdx.z;
    const float* s = src + (size_t)z * sstride;
    size_t dbase = (size_t)z * dstride;
    int c0 = blockIdx.x * 32;    // output-row (source col) base
    int r0 = blockIdx.y * 64;    // K (source row) base
    const int tid = threadIdx.x;

    // load: 64 rows x 32 cols; coalesced 128B per source-row segment
#pragma unroll
    for (int i = 0; i < 8; i++) {
        int idx = tid + 256 * i;
        int k = idx >> 5, n = idx & 31;
        tile[k][n] = s[(size_t)(r0 + k) * C + c0 + n];
    }
    __syncthreads();

    // write: 32 output rows x 64 K-values; each warp writes 128B contiguous
#pragma unroll
    for (int j = 0; j < 4; j++) {
        int n  = (tid >> 5) + 8 * j;
        int m2 = tid & 31;
        float v0 = tile[2 * m2][n];
        float v1 = tile[2 * m2 + 1][n];
        int r = c0 + n;
        int rr = (goff >= 0) ? (((r >> 5) << 6) + goff + (r & 31)) : r;
        __half2 hv = __halves2half2(__float2half_rn(v0), __float2half_rn(v1));
        *(__half2*)&dst[dbase + (size_t)rr * R + r0 + 2 * m2] = hv;
    }
}

__global__ void k_xsplit(const float* __restrict__ x) {
    int i = blockIdx.x * blockDim.x + threadIdx.x;
    g_x[i] = __float2half_rn(x[i]);
}

// ============================ GEMM tiles ================================
#define LDT 40          // smem row stride in fp16 elems (80B, conflict-free ldmatrix)
#define NSTG 4

// ---- GEMM1: 128(M) x 128(W'-rows) x 32, warps 4(M) x 2(N) ----
#define G1_A    0
#define G1_B    5120                  // 128 rows x LDT
#define G1_STG  10240                 // elems / stage
#define G1_STGB (G1_STG * 2)          // 20480 bytes / stage
#define G1_SMEM (NSTG * G1_STGB + 512)

__global__ __launch_bounds__(256, 2) void k_gemm1() {
    const int z   = blockIdx.z;
    const int m0  = blockIdx.y * 128;
    const int n0p = blockIdx.x * 128;     // W' row base
    const int M   = (z < NEXP) ? g_cnt[z] : TOK;
    if (m0 >= M) return;
    const size_t rowbase = (z < NEXP) ? ((size_t)z * TOK + m0) : ((size_t)ROWCAP + m0);

    extern __shared__ __align__(16) char sm[];
    int* stok = (int*)(sm + NSTG * G1_STGB);
    const int tid = threadIdx.x;
    if (tid < 128) {
        int r = m0 + tid; if (r > M - 1) r = M - 1;
        stok[tid] = (z < NEXP) ? g_tok[z * TOK + r] : r;
    }
    __syncthreads();

    const uint32_t sbu = smem_u32(sm);
    const int ra = tid >> 2, c4 = tid & 3;
    const int tA0 = stok[ra], tA1 = stok[64 + ra];
    const __half* sx0 = g_x + (size_t)tA0 * DDIM + c4 * 8;
    const __half* sx1 = g_x + (size_t)tA1 * DDIM + c4 * 8;
    const size_t bsrc = ((size_t)z * 2 * FDIM + n0p + ra) * DDIM + c4 * 8;
    const __half *sB0 = g_wgT + bsrc, *sB1 = sB0 + (size_t)64 * DDIM;

    const uint32_t dA0 = (G1_A + ra * LDT + c4 * 8) * 2;
    const uint32_t dA1 = dA0 + 64 * LDT * 2;
    const uint32_t dB0 = (G1_B + ra * LDT + c4 * 8) * 2;
    const uint32_t dB1 = dB0 + 64 * LDT * 2;

    const int lane = tid & 31, w = tid >> 5;
    const int wm = w >> 1, wn = w & 1;
    const int qr = lane >> 2, qc = lane & 3;
    const uint32_t aoff = ((wm * 32 + (lane & 15)) * LDT + (lane >> 4) * 8) * 2;
    const uint32_t boff = (G1_B + (wn * 64 + (lane & 7) + ((lane >> 4) & 1) * 8) * LDT
                           + ((lane >> 3) & 1) * 8) * 2;

    float acc[2][8][4] = {};

#define G1_LOAD(it) do { \
    const int k0 = (it) * 32; \
    const uint32_t db = sbu + ((it) % NSTG) * G1_STGB; \
    CP16(db + dA0, sx0 + k0); \
    CP16(db + dA1, sx1 + k0); \
    CP16(db + dB0, sB0 + k0); \
    CP16(db + dB1, sB1 + k0); \
    CPCOMMIT(); \
} while (0)

    G1_LOAD(0);
    G1_LOAD(1);
    G1_LOAD(2);

    const int NIT = DDIM / 32;
    for (int it = 0; it < NIT; it++) {
        CPWAIT2();
        __syncthreads();
        if (it + 3 < NIT) G1_LOAD(it + 3); else CPCOMMIT();
        const uint32_t stg = sbu + (it % NSTG) * G1_STGB;
#pragma unroll
        for (int ks = 0; ks < 32; ks += 16) {
            uint32_t ah[2][4];
#pragma unroll
            for (int mt = 0; mt < 2; mt++)
                ldsm4(ah[mt], stg + aoff + mt * (16 * LDT * 2) + ks * 2);
#pragma unroll
            for (int nh = 0; nh < 4; nh++) {
                uint32_t bb[4];
                ldsm4(bb, stg + boff + nh * (16 * LDT * 2) + ks * 2);
#pragma unroll
                for (int t = 0; t < 2; t++) {
                    const int nt = nh * 2 + t;
#pragma unroll
                    for (int mt = 0; mt < 2; mt++)
                        mma_f16(acc[mt][nt], ah[mt], bb + 2 * t);
                }
            }
        }
    }
#undef G1_LOAD

    // epilogue: GLU pairing in-register: g = acc[mt][nt], u = acc[mt][nt+4]
    const int fb = blockIdx.x * 64 + wn * 32;
#pragma unroll
    for (int mt = 0; mt < 2; mt++)
#pragma unroll
        for (int nt = 0; nt < 4; nt++) {
            const int R = wm * 32 + mt * 16 + qr;
            const int C = fb + nt * 8 + 2 * qc;
#pragma unroll
            for (int half = 0; half < 2; half++) {
                const int r = R + half * 8;
                float g0 = acc[mt][nt][2 * half],     u0 = acc[mt][nt + 4][2 * half];
                float g1 = acc[mt][nt][2 * half + 1], u1 = acc[mt][nt + 4][2 * half + 1];
                float o0 = g0 / (1.f + __expf(-g0)) * u0;
                float o1 = g1 / (1.f + __expf(-g1)) * u1;
                const size_t idx = (rowbase + r) * (size_t)FDIM + C;
                *(unsigned*)&g_h[idx] = pk2h(__float2half_rn(o0), __float2half_rn(o1));
            }
        }
}

// ---- GEMM2: 128 x 64 x 32, warps 4 x 2 over (32M x 32N) ----
#define G2_A    0
#define G2_B    5120
#define G2_STG  7680
#define G2_STGB (G2_STG * 2)
#define G2_SMEM (NSTG * G2_STGB)

__global__ __launch_bounds__(256, 2) void k_gemm2() {
    const int z  = blockIdx.z;
    const int m0 = blockIdx.y * 128;
    const int n0 = blockIdx.x * 64;
    const int M  = (z < NEXP) ? g_cnt[z] : TOK;
    if (m0 >= M) return;
    const size_t rowbase = (z < NEXP) ? ((size_t)z * TOK + m0) : ((size_t)ROWCAP + m0);

    extern __shared__ __align__(16) char sm[];
    const uint32_t sbu = smem_u32(sm);
    const int tid = threadIdx.x;
    const int ra = tid >> 2, c4 = tid & 3;

    const __half* sa0 = g_h + (rowbase + ra) * (size_t)FDIM + c4 * 8;
    const __half* sa1 = g_h + (rowbase + 64 + ra) * (size_t)FDIM + c4 * 8;
    const size_t bsrc = ((size_t)z * DDIM + n0 + ra) * FDIM + c4 * 8;
    const __half* sB = g_w2T + bsrc;

    const uint32_t dA0 = (G2_A + ra * LDT + c4 * 8) * 2;
    const uint32_t dA1 = dA0 + 64 * LDT * 2;
    const uint32_t dB  = (G2_B + ra * LDT + c4 * 8) * 2;

    const int lane = tid & 31, w = tid >> 5;
    const int wm = w >> 1, wn = w & 1;
    const int qr = lane >> 2, qc = lane & 3;
    const uint32_t aoff = ((wm * 32 + (lane & 15)) * LDT + (lane >> 4) * 8) * 2;
    const uint32_t boff = (G2_B + (wn * 32 + (lane & 7) + ((lane >> 4) & 1) * 8) * LDT
                           + ((lane >> 3) & 1) * 8) * 2;

    float acc[2][4][4] = {};

#define G2_LOAD(it) do { \
    const int k0 = (it) * 32; \
    const uint32_t db = sbu + ((it) % NSTG) * G2_STGB; \
    CP16(db + dA0, sa0 + k0); \
    CP16(db + dA1, sa1 + k0); \
    CP16(db + dB, sB + k0); \
    CPCOMMIT(); \
} while (0)

    G2_LOAD(0);
    G2_LOAD(1);
    G2_LOAD(2);

    const int NIT = FDIM / 32;
    for (int it = 0; it < NIT; it++) {
        CPWAIT2();
        __syncthreads();
        if (it + 3 < NIT) G2_LOAD(it + 3); else CPCOMMIT();
        const uint32_t stg = sbu + (it % NSTG) * G2_STGB;
#pragma unroll
        for (int ks = 0; ks < 32; ks += 16) {
            uint32_t ah[2][4];
#pragma unroll
            for (int mt = 0; mt < 2; mt++)
                ldsm4(ah[mt], stg + aoff + mt * (16 * LDT * 2) + ks * 2);
#pragma unroll
            for (int nh = 0; nh < 2; nh++) {
                uint32_t bb[4];
                ldsm4(bb, stg + boff + nh * (16 * LDT * 2) + ks * 2);
#pragma unroll
                for (int t = 0; t < 2; t++) {
                    const int nt = nh * 2 + t;
#pragma unroll
                    for (int mt = 0; mt < 2; mt++)
                        mma_f16(acc[mt][nt], ah[mt], bb + 2 * t);
                }
            }
        }
    }
#undef G2_LOAD

#pragma unroll
    for (int mt = 0; mt < 2; mt++)
#pragma unroll
        for (int nt = 0; nt < 4; nt++) {
            const int R = wm * 32 + mt * 16 + qr;
            const int C = wn * 32 + nt * 8 + 2 * qc;
#pragma unroll
            for (int half = 0; half < 2; half++) {
                const int r = R + half * 8;
                float2 o;
                o.x = acc[mt][nt][2 * half];
                o.y = acc[mt][nt][2 * half + 1];
                *(float2*)&g_orow[(rowbase + r) * (size_t)DDIM + n0 + C] = o;
            }
        }
}

// ============================ combine ===================================
__global__ void k_combine(float* __restrict__ out) {
    int idx = blockIdx.x * blockDim.x + threadIdx.x;
    if (idx >= TOK * DDIM) return;
    int t = idx >> 10;
    int d = idx & (DDIM - 1);
    float sh = g_orow[((size_t)ROWCAP + t) * DDIM + d];
    int   r0 = g_rowof[2 * t], r1 = g_rowof[2 * t + 1];
    float v = 0.0625f * sh
            + 0.5f * (g_gw[2 * t] * g_orow[(size_t)r0 * DDIM + d]
                    + g_gw[2 * t + 1] * g_orow[(size_t)r1 * DDIM + d]);
    out[idx] = v;
}

// ============================ launch ====================================
extern "C" void kernel_launch(void* const* d_in, const int* in_sizes, int n_in,
                              void* d_out, int out_size) {
    const float* x   = (const float*)d_in[0];
    const float* gW  = (const float*)d_in[1];
    const float* w1e = (const float*)d_in[2];
    const float* w3e = (const float*)d_in[3];
    const float* w2e = (const float*)d_in[4];
    const float* w1s = (const float*)d_in[5];
    const float* w3s = (const float*)d_in[6];
    const float* w2s = (const float*)d_in[7];
    float* out = (float*)d_out;

    cudaFuncSetAttribute(k_gemm1, cudaFuncAttributeMaxDynamicSharedMemorySize, G1_SMEM);
    cudaFuncSetAttribute(k_gemm2, cudaFuncAttributeMaxDynamicSharedMemorySize, G2_SMEM);

    k_reset<<<1, 32>>>();
    k_gate<<<TOK / 8, 256>>>(x, gW);
    k_xsplit<<<TOK * DDIM / 256, 256>>>(x);

    // routed: w1/w3 -> interleaved W' slots 0..7; w2 -> w2T slots 0..7
    // grids: x = source-cols/32 (output rows), y = source-rows/64 (K)
    k_transplit<<<dim3(FDIM / 32, DDIM / 64, NEXP), 256>>>(
        w1e, 0, 0, DDIM, FDIM, (size_t)DDIM * FDIM, (size_t)2 * FDIM * DDIM, 0);
    k_transplit<<<dim3(FDIM / 32, DDIM / 64, NEXP), 256>>>(
        w3e, 0, 0, DDIM, FDIM, (size_t)DDIM * FDIM, (size_t)2 * FDIM * DDIM, 32);
    k_transplit<<<dim3(DDIM / 32, FDIM / 64, NEXP), 256>>>(
        w2e, 1, 0, FDIM, DDIM, (size_t)FDIM * DDIM, (size_t)DDIM * FDIM, -1);
    // shared experts -> slot 8 (block-concatenated); per-z W' span = 1024 rows
    k_transplit<<<dim3(FSH / 32, DDIM / 64, NEXP), 256>>>(
        w1s, 0, (size_t)NEXP * 2 * FDIM * DDIM, DDIM, FSH, (size_t)DDIM * FSH,
        (size_t)1024 * DDIM, 0);
    k_transplit<<<dim3(FSH / 32, DDIM / 64, NEXP), 256>>>(
        w3s, 0, (size_t)NEXP * 2 * FDIM * DDIM, DDIM, FSH, (size_t)DDIM * FSH,
        (size_t)1024 * DDIM, 32);
    k_transplit<<<dim3(DDIM / 32, FDIM / 64, 1), 256>>>(
        w2s, 1, (size_t)NEXP * DDIM * FDIM, FDIM, DDIM, 0, 0, -1);

    k_gemm1<<<dim3(2 * FDIM / 128, TOK / 128, NSLOT), 256, G1_SMEM>>>();
    k_gemm2<<<dim3(DDIM / 64, TOK / 128, NSLOT), 256, G2_SMEM>>>();
    k_combine<<<(TOK * DDIM) / 256, 256>>>(out);
}

// round 15
// speedup vs baseline: 1.3767x; 1.0297x over previous
#include <cuda_runtime.h>
#include <cuda_fp16.h>
#include <math.h>
#include <cstdint>
#include <string.h>

// ---------------- problem constants ----------------
#define TOK   2048
#define DDIM  1024
#define FDIM  4096
#define NEXP  8
#define FSH   512
#define TOPK  2
#define ROWCAP (NEXP*TOK)
#define NROWS  (ROWCAP + TOK)
#define NSLOT  9          // 8 routed + merged shared (slot 8)

// ---------------- scratch (device globals) ----------------
__device__ int   g_cnt[NEXP];
__device__ int   g_tok[ROWCAP];
__device__ int   g_rowof[TOK * TOPK];
__device__ float g_gw[TOK * TOPK];
__device__ __half g_x[TOK * DDIM];
// W' : per slot 2*FDIM rows (g/u interleaved in 32-row blocks), K-major [r'][D]
__device__ __half g_wgT[(size_t)NSLOT * 2 * FDIM * DDIM];
__device__ __half g_w2T[(size_t)NSLOT * DDIM * FDIM];   // [slot][D][F] fp16
__device__ __half g_h[(size_t)NROWS * FDIM];
__device__ float g_orow[(size_t)NROWS * DDIM];

// ---------------- helpers ----------------
__device__ __forceinline__ uint32_t smem_u32(const void* p) {
    uint32_t a;
    asm("{ .reg .u64 t; cvta.to.shared.u64 t, %1; cvt.u32.u64 %0, t; }" : "=r"(a) : "l"(p));
    return a;
}
__device__ __forceinline__ void ldsm4(uint32_t* r, uint32_t a) {
    asm volatile("ldmatrix.sync.aligned.m8n8.x4.shared.b16 {%0,%1,%2,%3}, [%4];"
                 : "=r"(r[0]), "=r"(r[1]), "=r"(r[2]), "=r"(r[3]) : "r"(a));
}
__device__ __forceinline__ void mma_f16(float* c, const uint32_t* a, const uint32_t* b) {
    asm volatile(
        "mma.sync.aligned.m16n8k16.row.col.f32.f16.f16.f32 "
        "{%0,%1,%2,%3},{%4,%5,%6,%7},{%8,%9},{%0,%1,%2,%3};"
        : "+f"(c[0]), "+f"(c[1]), "+f"(c[2]), "+f"(c[3])
        : "r"(a[0]), "r"(a[1]), "r"(a[2]), "r"(a[3]), "r"(b[0]), "r"(b[1]));
}
#define CP16(dst, src) \
    asm volatile("cp.async.cg.shared.global [%0], [%1], 16;" :: "r"(dst), "l"(src))
#define CPCOMMIT() asm volatile("cp.async.commit_group;" ::: "memory")
#define CPWAIT2()  asm volatile("cp.async.wait_group 2;" ::: "memory")

__device__ __forceinline__ unsigned pk2h(__half a, __half b) {
    __half2 t = __halves2half2(a, b);
    unsigned r; memcpy(&r, &t, 4); return r;
}

// ============================ reset / gate ===============================
__global__ void k_reset() {
    if (threadIdx.x < NEXP) g_cnt[threadIdx.x] = 0;
}

__global__ void k_gate(const float* __restrict__ x, const float* __restrict__ gateW) {
    int gwarp = (blockIdx.x * blockDim.x + threadIdx.x) >> 5;
    int lane  = threadIdx.x & 31;
    if (gwarp >= TOK) return;
    const float* xr = x + (size_t)gwarp * DDIM;
    float xv[32];
#pragma unroll
    for (int i = 0; i < 32; i++) xv[i] = xr[lane + 32 * i];
    float logit[NEXP];
#pragma unroll
    for (int e = 0; e < NEXP; e++) {
        const float* wr = gateW + e * DDIM;
        float acc = 0.f;
#pragma unroll
        for (int i = 0; i < 32; i++) acc += xv[i] * wr[lane + 32 * i];
#pragma unroll
        for (int o = 16; o > 0; o >>= 1) acc += __shfl_xor_sync(0xffffffffu, acc, o);
        logit[e] = acc;
    }
    if (lane == 0) {
        float m = logit[0];
#pragma unroll
        for (int e = 1; e < NEXP; e++) m = fmaxf(m, logit[e]);
        float p[NEXP], den = 0.f;
#pragma unroll
        for (int e = 0; e < NEXP; e++) { p[e] = expf(logit[e] - m); den += p[e]; }
        int i1 = 0;
#pragma unroll
        for (int e = 1; e < NEXP; e++) if (p[e] > p[i1]) i1 = e;
        int i2 = (i1 == 0) ? 1 : 0;
#pragma unroll
        for (int e = 0; e < NEXP; e++) if (e != i2 && e != i1 && p[e] > p[i2]) i2 = e;
        int pos1 = atomicAdd(&g_cnt[i1], 1);
        int r1 = i1 * TOK + pos1;
        g_tok[r1] = gwarp;
        g_rowof[2 * gwarp + 0] = r1;
        g_gw[2 * gwarp + 0] = p[i1] / den;
        int pos2 = atomicAdd(&g_cnt[i2], 1);
        int r2 = i2 * TOK + pos2;
        g_tok[r2] = gwarp;
        g_rowof[2 * gwarp + 1] = r2;
        g_gw[2 * gwarp + 1] = p[i2] / den;
    }
}

// ===================== weight transpose (fp16) v2 ========================
__global__ __launch_bounds__(256) void k_transplit(
    const float* __restrict__ src, int dst_id, size_t extra,
    int R, int C, size_t sstride, size_t dstride, int goff)
{
    __shared__ float tile[64][33];
    __half* dst = (dst_id == 0) ? g_wgT : g_w2T;
    dst += extra;

    int z = blockIdx.z;
    const float* s = src + (size_t)z * sstride;
    size_t dbase = (size_t)z * dstride;
    int c0 = blockIdx.x * 32;    // output-row (source col) base
    int r0 = blockIdx.y * 64;    // K (source row) base
    const int tid = threadIdx.x;

#pragma unroll
    for (int i = 0; i < 8; i++) {
        int idx = tid + 256 * i;
        int k = idx >> 5, n = idx & 31;
        tile[k][n] = s[(size_t)(r0 + k) * C + c0 + n];
    }
    __syncthreads();

#pragma unroll
    for (int j = 0; j < 4; j++) {
        int n  = (tid >> 5) + 8 * j;
        int m2 = tid & 31;
        float v0 = tile[2 * m2][n];
        float v1 = tile[2 * m2 + 1][n];
        int r = c0 + n;
        int rr = (goff >= 0) ? (((r >> 5) << 6) + goff + (r & 31)) : r;
        __half2 hv = __halves2half2(__float2half_rn(v0), __float2half_rn(v1));
        *(__half2*)&dst[dbase + (size_t)rr * R + r0 + 2 * m2] = hv;
    }
}

__global__ void k_xsplit(const float* __restrict__ x) {
    int i = blockIdx.x * blockDim.x + threadIdx.x;
    g_x[i] = __float2half_rn(x[i]);
}

// ============================ GEMM tiles ================================
#define LDT 40          // smem row stride in fp16 elems (80B, conflict-free ldmatrix)
#define NSTG 4

// ---- GEMM1: 128(M) x 128(W'-rows) x 32, warps 4(M) x 2(N) ----
#define G1_A    0
#define G1_B    5120                  // 128 rows x LDT
#define G1_STG  10240                 // elems / stage
#define G1_STGB (G1_STG * 2)          // 20480 bytes / stage
#define G1_SMEM (NSTG * G1_STGB + 512)

__global__ __launch_bounds__(256, 2) void k_gemm1() {
    const int z   = blockIdx.z;
    const int m0  = blockIdx.y * 128;
    const int n0p = blockIdx.x * 128;     // W' row base
    const int M   = (z < NEXP) ? g_cnt[z] : TOK;
    if (m0 >= M) return;
    const size_t rowbase = (z < NEXP) ? ((size_t)z * TOK + m0) : ((size_t)ROWCAP + m0);

    extern __shared__ __align__(16) char sm[];
    int* stok = (int*)(sm + NSTG * G1_STGB);
    const int tid = threadIdx.x;
    if (tid < 128) {
        int r = m0 + tid; if (r > M - 1) r = M - 1;
        stok[tid] = (z < NEXP) ? g_tok[z * TOK + r] : r;
    }
    __syncthreads();

    const uint32_t sbu = smem_u32(sm);
    const int ra = tid >> 2, c4 = tid & 3;
    const int tA0 = stok[ra], tA1 = stok[64 + ra];
    const __half* sx0 = g_x + (size_t)tA0 * DDIM + c4 * 8;
    const __half* sx1 = g_x + (size_t)tA1 * DDIM + c4 * 8;
    const size_t bsrc = ((size_t)z * 2 * FDIM + n0p + ra) * DDIM + c4 * 8;
    const __half *sB0 = g_wgT + bsrc, *sB1 = sB0 + (size_t)64 * DDIM;

    const uint32_t dA0 = (G1_A + ra * LDT + c4 * 8) * 2;
    const uint32_t dA1 = dA0 + 64 * LDT * 2;
    const uint32_t dB0 = (G1_B + ra * LDT + c4 * 8) * 2;
    const uint32_t dB1 = dB0 + 64 * LDT * 2;

    const int lane = tid & 31, w = tid >> 5;
    const int wm = w >> 1, wn = w & 1;
    const int qr = lane >> 2, qc = lane & 3;
    const uint32_t aoff = ((wm * 32 + (lane & 15)) * LDT + (lane >> 4) * 8) * 2;
    const uint32_t boff = (G1_B + (wn * 64 + (lane & 7) + ((lane >> 4) & 1) * 8) * LDT
                           + ((lane >> 3) & 1) * 8) * 2;

    float acc[2][8][4] = {};

#define G1_LOAD(it) do { \
    const int k0 = (it) * 32; \
    const uint32_t db = sbu + ((it) % NSTG) * G1_STGB; \
    CP16(db + dA0, sx0 + k0); \
    CP16(db + dA1, sx1 + k0); \
    CP16(db + dB0, sB0 + k0); \
    CP16(db + dB1, sB1 + k0); \
    CPCOMMIT(); \
} while (0)

    G1_LOAD(0);
    G1_LOAD(1);
    G1_LOAD(2);

    const int NIT = DDIM / 32;
    for (int it = 0; it < NIT; it++) {
        CPWAIT2();
        __syncthreads();
        if (it + 3 < NIT) G1_LOAD(it + 3); else CPCOMMIT();
        const uint32_t stg = sbu + (it % NSTG) * G1_STGB;
#pragma unroll
        for (int ks = 0; ks < 32; ks += 16) {
            uint32_t ah[2][4];
#pragma unroll
            for (int mt = 0; mt < 2; mt++)
                ldsm4(ah[mt], stg + aoff + mt * (16 * LDT * 2) + ks * 2);
#pragma unroll
            for (int nh = 0; nh < 4; nh++) {
                uint32_t bb[4];
                ldsm4(bb, stg + boff + nh * (16 * LDT * 2) + ks * 2);
#pragma unroll
                for (int t = 0; t < 2; t++) {
                    const int nt = nh * 2 + t;
#pragma unroll
                    for (int mt = 0; mt < 2; mt++)
                        mma_f16(acc[mt][nt], ah[mt], bb + 2 * t);
                }
            }
        }
    }
#undef G1_LOAD

    // epilogue: GLU pairing in-register: g = acc[mt][nt], u = acc[mt][nt+4]
    const int fb = blockIdx.x * 64 + wn * 32;
#pragma unroll
    for (int mt = 0; mt < 2; mt++)
#pragma unroll
        for (int nt = 0; nt < 4; nt++) {
            const int R = wm * 32 + mt * 16 + qr;
            const int C = fb + nt * 8 + 2 * qc;
#pragma unroll
            for (int half = 0; half < 2; half++) {
                const int r = R + half * 8;
                float g0 = acc[mt][nt][2 * half],     u0 = acc[mt][nt + 4][2 * half];
                float g1 = acc[mt][nt][2 * half + 1], u1 = acc[mt][nt + 4][2 * half + 1];
                float o0 = g0 / (1.f + __expf(-g0)) * u0;
                float o1 = g1 / (1.f + __expf(-g1)) * u1;
                const size_t idx = (rowbase + r) * (size_t)FDIM + C;
                *(unsigned*)&g_h[idx] = pk2h(__float2half_rn(o0), __float2half_rn(o1));
            }
        }
}

// ---- GEMM2: 128(M) x 128(N) x 32, warps 4(M) x 2(N), each warp 32Mx64N ----
#define G2_A    0
#define G2_B    5120
#define G2_STG  10240
#define G2_STGB (G2_STG * 2)
#define G2_SMEM (NSTG * G2_STGB)

__global__ __launch_bounds__(256, 2) void k_gemm2() {
    const int z  = blockIdx.z;
    const int m0 = blockIdx.y * 128;
    const int n0 = blockIdx.x * 128;
    const int M  = (z < NEXP) ? g_cnt[z] : TOK;
    if (m0 >= M) return;
    const size_t rowbase = (z < NEXP) ? ((size_t)z * TOK + m0) : ((size_t)ROWCAP + m0);

    extern __shared__ __align__(16) char sm[];
    const uint32_t sbu = smem_u32(sm);
    const int tid = threadIdx.x;
    const int ra = tid >> 2, c4 = tid & 3;

    const __half* sa0 = g_h + (rowbase + ra) * (size_t)FDIM + c4 * 8;
    const __half* sa1 = g_h + (rowbase + 64 + ra) * (size_t)FDIM + c4 * 8;
    const size_t bsrc = ((size_t)z * DDIM + n0 + ra) * FDIM + c4 * 8;
    const __half *sB0 = g_w2T + bsrc, *sB1 = sB0 + (size_t)64 * FDIM;

    const uint32_t dA0 = (G2_A + ra * LDT + c4 * 8) * 2;
    const uint32_t dA1 = dA0 + 64 * LDT * 2;
    const uint32_t dB0 = (G2_B + ra * LDT + c4 * 8) * 2;
    const uint32_t dB1 = dB0 + 64 * LDT * 2;

    const int lane = tid & 31, w = tid >> 5;
    const int wm = w >> 1, wn = w & 1;
    const int qr = lane >> 2, qc = lane & 3;
    const uint32_t aoff = ((wm * 32 + (lane & 15)) * LDT + (lane >> 4) * 8) * 2;
    const uint32_t boff = (G2_B + (wn * 64 + (lane & 7) + ((lane >> 4) & 1) * 8) * LDT
                           + ((lane >> 3) & 1) * 8) * 2;

    float acc[2][8][4] = {};

#define G2_LOAD(it) do { \
    const int k0 = (it) * 32; \
    const uint32_t db = sbu + ((it) % NSTG) * G2_STGB; \
    CP16(db + dA0, sa0 + k0); \
    CP16(db + dA1, sa1 + k0); \
    CP16(db + dB0, sB0 + k0); \
    CP16(db + dB1, sB1 + k0); \
    CPCOMMIT(); \
} while (0)

    G2_LOAD(0);
    G2_LOAD(1);
    G2_LOAD(2);

    const int NIT = FDIM / 32;
    for (int it = 0; it < NIT; it++) {
        CPWAIT2();
        __syncthreads();
        if (it + 3 < NIT) G2_LOAD(it + 3); else CPCOMMIT();
        const uint32_t stg = sbu + (it % NSTG) * G2_STGB;
#pragma unroll
        for (int ks = 0; ks < 32; ks += 16) {
            uint32_t ah[2][4];
#pragma unroll
            for (int mt = 0; mt < 2; mt++)
                ldsm4(ah[mt], stg + aoff + mt * (16 * LDT * 2) + ks * 2);
#pragma unroll
            for (int nh = 0; nh < 4; nh++) {
                uint32_t bb[4];
                ldsm4(bb, stg + boff + nh * (16 * LDT * 2) + ks * 2);
#pragma unroll
                for (int t = 0; t < 2; t++) {
                    const int nt = nh * 2 + t;
#pragma unroll
                    for (int mt = 0; mt < 2; mt++)
                        mma_f16(acc[mt][nt], ah[mt], bb + 2 * t);
                }
            }
        }
    }
#undef G2_LOAD

#pragma unroll
    for (int mt = 0; mt < 2; mt++)
#pragma unroll
        for (int nt = 0; nt < 8; nt++) {
            const int R = wm * 32 + mt * 16 + qr;
            const int C = n0 + wn * 64 + nt * 8 + 2 * qc;
#pragma unroll
            for (int half = 0; half < 2; half++) {
                const int r = R + half * 8;
                float2 o;
                o.x = acc[mt][nt][2 * half];
                o.y = acc[mt][nt][2 * half + 1];
                *(float2*)&g_orow[(rowbase + r) * (size_t)DDIM + C] = o;
            }
        }
}

// ============================ combine ===================================
__global__ void k_combine(float* __restrict__ out) {
    int idx = blockIdx.x * blockDim.x + threadIdx.x;
    if (idx >= TOK * DDIM) return;
    int t = idx >> 10;
    int d = idx & (DDIM - 1);
    float sh = g_orow[((size_t)ROWCAP + t) * DDIM + d];
    int   r0 = g_rowof[2 * t], r1 = g_rowof[2 * t + 1];
    float v = 0.0625f * sh
            + 0.5f * (g_gw[2 * t] * g_orow[(size_t)r0 * DDIM + d]
                    + g_gw[2 * t + 1] * g_orow[(size_t)r1 * DDIM + d]);
    out[idx] = v;
}

// ============================ launch ====================================
extern "C" void kernel_launch(void* const* d_in, const int* in_sizes, int n_in,
                              void* d_out, int out_size) {
    const float* x   = (const float*)d_in[0];
    const float* gW  = (const float*)d_in[1];
    const float* w1e = (const float*)d_in[2];
    const float* w3e = (const float*)d_in[3];
    const float* w2e = (const float*)d_in[4];
    const float* w1s = (const float*)d_in[5];
    const float* w3s = (const float*)d_in[6];
    const float* w2s = (const float*)d_in[7];
    float* out = (float*)d_out;

    cudaFuncSetAttribute(k_gemm1, cudaFuncAttributeMaxDynamicSharedMemorySize, G1_SMEM);
    cudaFuncSetAttribute(k_gemm2, cudaFuncAttributeMaxDynamicSharedMemorySize, G2_SMEM);

    k_reset<<<1, 32>>>();
    k_gate<<<TOK / 8, 256>>>(x, gW);
    k_xsplit<<<TOK * DDIM / 256, 256>>>(x);

    // routed: w1/w3 -> interleaved W' slots 0..7; w2 -> w2T slots 0..7
    // grids: x = source-cols/32 (output rows), y = source-rows/64 (K)
    k_transplit<<<dim3(FDIM / 32, DDIM / 64, NEXP), 256>>>(
        w1e, 0, 0, DDIM, FDIM, (size_t)DDIM * FDIM, (size_t)2 * FDIM * DDIM, 0);
    k_transplit<<<dim3(FDIM / 32, DDIM / 64, NEXP), 256>>>(
        w3e, 0, 0, DDIM, FDIM, (size_t)DDIM * FDIM, (size_t)2 * FDIM * DDIM, 32);
    k_transplit<<<dim3(DDIM / 32, FDIM / 64, NEXP), 256>>>(
        w2e, 1, 0, FDIM, DDIM, (size_t)FDIM * DDIM, (size_t)DDIM * FDIM, -1);
    // shared experts -> slot 8 (block-concatenated); per-z W' span = 1024 rows
    k_transplit<<<dim3(FSH / 32, DDIM / 64, NEXP), 256>>>(
        w1s, 0, (size_t)NEXP * 2 * FDIM * DDIM, DDIM, FSH, (size_t)DDIM * FSH,
        (size_t)1024 * DDIM, 0);
    k_transplit<<<dim3(FSH / 32, DDIM / 64, NEXP), 256>>>(
        w3s, 0, (size_t)NEXP * 2 * FDIM * DDIM, DDIM, FSH, (size_t)DDIM * FSH,
        (size_t)1024 * DDIM, 32);
    k_transplit<<<dim3(DDIM / 32, FDIM / 64, 1), 256>>>(
        w2s, 1, (size_t)NEXP * DDIM * FDIM, FDIM, DDIM, 0, 0, -1);

    k_gemm1<<<dim3(2 * FDIM / 128, TOK / 128, NSLOT), 256, G1_SMEM>>>();
    k_gemm2<<<dim3(DDIM / 128, TOK / 128, NSLOT), 256, G2_SMEM>>>();
    k_combine<<<(TOK * DDIM) / 256, 256>>>(out);
}

// round 16
// speedup vs baseline: 1.4092x; 1.0235x over previous
#include <cuda_runtime.h>
#include <cuda_fp16.h>
#include <math.h>
#include <cstdint>
#include <string.h>

// ---------------- problem constants ----------------
#define TOK   2048
#define DDIM  1024
#define FDIM  4096
#define NEXP  8
#define FSH   512
#define TOPK  2
#define ROWCAP (NEXP*TOK)
#define NROWS  (ROWCAP + TOK)
#define NSLOT  9          // 8 routed + merged shared (slot 8)

// ---------------- scratch (device globals) ----------------
__device__ int   g_cnt[NEXP];
__device__ int   g_tok[ROWCAP];
__device__ int   g_rowof[TOK * TOPK];
__device__ float g_gw[TOK * TOPK];
__device__ __half g_x[TOK * DDIM];
// W' : per slot 2*FDIM rows (g/u interleaved in 32-row blocks), K-major [r'][D]
__device__ __half g_wgT[(size_t)NSLOT * 2 * FDIM * DDIM];
__device__ __half g_w2T[(size_t)NSLOT * DDIM * FDIM];   // [slot][D][F] fp16
__device__ __half g_h[(size_t)NROWS * FDIM];
__device__ float g_orow[(size_t)NROWS * DDIM];

// ---------------- helpers ----------------
__device__ __forceinline__ uint32_t smem_u32(const void* p) {
    uint32_t a;
    asm("{ .reg .u64 t; cvta.to.shared.u64 t, %1; cvt.u32.u64 %0, t; }" : "=r"(a) : "l"(p));
    return a;
}
__device__ __forceinline__ void ldsm4(uint32_t* r, uint32_t a) {
    asm volatile("ldmatrix.sync.aligned.m8n8.x4.shared.b16 {%0,%1,%2,%3}, [%4];"
                 : "=r"(r[0]), "=r"(r[1]), "=r"(r[2]), "=r"(r[3]) : "r"(a));
}
__device__ __forceinline__ void mma_f16(float* c, const uint32_t* a, const uint32_t* b) {
    asm volatile(
        "mma.sync.aligned.m16n8k16.row.col.f32.f16.f16.f32 "
        "{%0,%1,%2,%3},{%4,%5,%6,%7},{%8,%9},{%0,%1,%2,%3};"
        : "+f"(c[0]), "+f"(c[1]), "+f"(c[2]), "+f"(c[3])
        : "r"(a[0]), "r"(a[1]), "r"(a[2]), "r"(a[3]), "r"(b[0]), "r"(b[1]));
}
#define CP16(dst, src) \
    asm volatile("cp.async.cg.shared.global [%0], [%1], 16;" :: "r"(dst), "l"(src))
#define CPCOMMIT() asm volatile("cp.async.commit_group;" ::: "memory")
#define CPWAIT2()  asm volatile("cp.async.wait_group 2;" ::: "memory")

__device__ __forceinline__ unsigned pk2h(__half a, __half b) {
    __half2 t = __halves2half2(a, b);
    unsigned r; memcpy(&r, &t, 4); return r;
}

// ============================ reset / gate ===============================
__global__ void k_reset() {
    if (threadIdx.x < NEXP) g_cnt[threadIdx.x] = 0;
}

// gate + x fp16 conversion fused (warp already holds full row)
__global__ void k_gate(const float* __restrict__ x, const float* __restrict__ gateW) {
    int gwarp = (blockIdx.x * blockDim.x + threadIdx.x) >> 5;
    int lane  = threadIdx.x & 31;
    if (gwarp >= TOK) return;
    const float* xr = x + (size_t)gwarp * DDIM;
    float xv[32];
#pragma unroll
    for (int i = 0; i < 32; i++) xv[i] = xr[lane + 32 * i];

    // fused xsplit: write fp16 copy of x
    __half* gx = g_x + (size_t)gwarp * DDIM + lane;
#pragma unroll
    for (int i = 0; i < 32; i++) gx[32 * i] = __float2half_rn(xv[i]);

    float logit[NEXP];
#pragma unroll
    for (int e = 0; e < NEXP; e++) {
        const float* wr = gateW + e * DDIM;
        float acc = 0.f;
#pragma unroll
        for (int i = 0; i < 32; i++) acc += xv[i] * wr[lane + 32 * i];
#pragma unroll
        for (int o = 16; o > 0; o >>= 1) acc += __shfl_xor_sync(0xffffffffu, acc, o);
        logit[e] = acc;
    }
    if (lane == 0) {
        float m = logit[0];
#pragma unroll
        for (int e = 1; e < NEXP; e++) m = fmaxf(m, logit[e]);
        float p[NEXP], den = 0.f;
#pragma unroll
        for (int e = 0; e < NEXP; e++) { p[e] = expf(logit[e] - m); den += p[e]; }
        int i1 = 0;
#pragma unroll
        for (int e = 1; e < NEXP; e++) if (p[e] > p[i1]) i1 = e;
        int i2 = (i1 == 0) ? 1 : 0;
#pragma unroll
        for (int e = 0; e < NEXP; e++) if (e != i2 && e != i1 && p[e] > p[i2]) i2 = e;
        int pos1 = atomicAdd(&g_cnt[i1], 1);
        int r1 = i1 * TOK + pos1;
        g_tok[r1] = gwarp;
        g_rowof[2 * gwarp + 0] = r1;
        g_gw[2 * gwarp + 0] = p[i1] / den;
        int pos2 = atomicAdd(&g_cnt[i2], 1);
        int r2 = i2 * TOK + pos2;
        g_tok[r2] = gwarp;
        g_rowof[2 * gwarp + 1] = r2;
        g_gw[2 * gwarp + 1] = p[i2] / den;
    }
}

// ===================== weight transpose (fp16) v3 ========================
// Source z-block: rows = K dim, cols = output-row dim. Tile: 64 K-rows x
// 64 source cols. 16 loads + 8 half2 stores per thread (high MLP).
// goff>=0 -> GLU 32-block interleave of output rows.
__global__ __launch_bounds__(256) void k_transplit(
    const float* __restrict__ src, int dst_id, size_t extra,
    int R, int C, size_t sstride, size_t dstride, int goff)
{
    __shared__ float tile[64][65];
    __half* dst = (dst_id == 0) ? g_wgT : g_w2T;
    dst += extra;

    int z = blockIdx.z;
    const float* s = src + (size_t)z * sstride;
    size_t dbase = (size_t)z * dstride;
    int c0 = blockIdx.x * 64;    // output-row (source col) base
    int r0 = blockIdx.y * 64;    // K (source row) base
    const int tid = threadIdx.x;

    // load: 64 rows x 64 cols; 128B coalesced segments
#pragma unroll
    for (int i = 0; i < 16; i++) {
        int idx = tid + 256 * i;
        int k = idx >> 6, n = idx & 63;
        tile[k][n] = s[(size_t)(r0 + k) * C + c0 + n];
    }
    __syncthreads();

    // write: 64 output rows x 64 K; each warp writes 128B contiguous per row
#pragma unroll
    for (int j = 0; j < 8; j++) {
        int n  = (tid >> 5) + 8 * j;
        int m2 = tid & 31;
        float v0 = tile[2 * m2][n];
        float v1 = tile[2 * m2 + 1][n];
        int r = c0 + n;
        int rr = (goff >= 0) ? (((r >> 5) << 6) + goff + (r & 31)) : r;
        __half2 hv = __halves2half2(__float2half_rn(v0), __float2half_rn(v1));
        *(__half2*)&dst[dbase + (size_t)rr * R + r0 + 2 * m2] = hv;
    }
}

// ============================ GEMM tiles ================================
#define LDT 40          // smem row stride in fp16 elems (80B, conflict-free ldmatrix)
#define NSTG 4

// ---- GEMM1: 128(M) x 128(W'-rows) x 32, warps 4(M) x 2(N) ----
#define G1_A    0
#define G1_B    5120                  // 128 rows x LDT
#define G1_STG  10240                 // elems / stage
#define G1_STGB (G1_STG * 2)          // 20480 bytes / stage
#define G1_SMEM (NSTG * G1_STGB + 512)

__global__ __launch_bounds__(256, 2) void k_gemm1() {
    const int z   = blockIdx.z;
    const int m0  = blockIdx.y * 128;
    const int n0p = blockIdx.x * 128;     // W' row base
    const int M   = (z < NEXP) ? g_cnt[z] : TOK;
    if (m0 >= M) return;
    const size_t rowbase = (z < NEXP) ? ((size_t)z * TOK + m0) : ((size_t)ROWCAP + m0);

    extern __shared__ __align__(16) char sm[];
    int* stok = (int*)(sm + NSTG * G1_STGB);
    const int tid = threadIdx.x;
    if (tid < 128) {
        int r = m0 + tid; if (r > M - 1) r = M - 1;
        stok[tid] = (z < NEXP) ? g_tok[z * TOK + r] : r;
    }
    __syncthreads();

    const uint32_t sbu = smem_u32(sm);
    const int ra = tid >> 2, c4 = tid & 3;
    const int tA0 = stok[ra], tA1 = stok[64 + ra];
    const __half* sx0 = g_x + (size_t)tA0 * DDIM + c4 * 8;
    const __half* sx1 = g_x + (size_t)tA1 * DDIM + c4 * 8;
    const size_t bsrc = ((size_t)z * 2 * FDIM + n0p + ra) * DDIM + c4 * 8;
    const __half *sB0 = g_wgT + bsrc, *sB1 = sB0 + (size_t)64 * DDIM;

    const uint32_t dA0 = (G1_A + ra * LDT + c4 * 8) * 2;
    const uint32_t dA1 = dA0 + 64 * LDT * 2;
    const uint32_t dB0 = (G1_B + ra * LDT + c4 * 8) * 2;
    const uint32_t dB1 = dB0 + 64 * LDT * 2;

    const int lane = tid & 31, w = tid >> 5;
    const int wm = w >> 1, wn = w & 1;
    const int qr = lane >> 2, qc = lane & 3;
    const uint32_t aoff = ((wm * 32 + (lane & 15)) * LDT + (lane >> 4) * 8) * 2;
    const uint32_t boff = (G1_B + (wn * 64 + (lane & 7) + ((lane >> 4) & 1) * 8) * LDT
                           + ((lane >> 3) & 1) * 8) * 2;

    float acc[2][8][4] = {};

#define G1_LOAD(it) do { \
    const int k0 = (it) * 32; \
    const uint32_t db = sbu + ((it) % NSTG) * G1_STGB; \
    CP16(db + dA0, sx0 + k0); \
    CP16(db + dA1, sx1 + k0); \
    CP16(db + dB0, sB0 + k0); \
    CP16(db + dB1, sB1 + k0); \
    CPCOMMIT(); \
} while (0)

    G1_LOAD(0);
    G1_LOAD(1);
    G1_LOAD(2);

    const int NIT = DDIM / 32;
    for (int it = 0; it < NIT; it++) {
        CPWAIT2();
        __syncthreads();
        if (it + 3 < NIT) G1_LOAD(it + 3); else CPCOMMIT();
        const uint32_t stg = sbu + (it % NSTG) * G1_STGB;
#pragma unroll
        for (int ks = 0; ks < 32; ks += 16) {
            uint32_t ah[2][4];
#pragma unroll
            for (int mt = 0; mt < 2; mt++)
                ldsm4(ah[mt], stg + aoff + mt * (16 * LDT * 2) + ks * 2);
#pragma unroll
            for (int nh = 0; nh < 4; nh++) {
                uint32_t bb[4];
                ldsm4(bb, stg + boff + nh * (16 * LDT * 2) + ks * 2);
#pragma unroll
                for (int t = 0; t < 2; t++) {
                    const int nt = nh * 2 + t;
#pragma unroll
                    for (int mt = 0; mt < 2; mt++)
                        mma_f16(acc[mt][nt], ah[mt], bb + 2 * t);
                }
            }
        }
    }
#undef G1_LOAD

    // epilogue: GLU pairing in-register: g = acc[mt][nt], u = acc[mt][nt+4]
    const int fb = blockIdx.x * 64 + wn * 32;
#pragma unroll
    for (int mt = 0; mt < 2; mt++)
#pragma unroll
        for (int nt = 0; nt < 4; nt++) {
            const int R = wm * 32 + mt * 16 + qr;
            const int C = fb + nt * 8 + 2 * qc;
#pragma unroll
            for (int half = 0; half < 2; half++) {
                const int r = R + half * 8;
                float g0 = acc[mt][nt][2 * half],     u0 = acc[mt][nt + 4][2 * half];
                float g1 = acc[mt][nt][2 * half + 1], u1 = acc[mt][nt + 4][2 * half + 1];
                float o0 = g0 / (1.f + __expf(-g0)) * u0;
                float o1 = g1 / (1.f + __expf(-g1)) * u1;
                const size_t idx = (rowbase + r) * (size_t)FDIM + C;
                *(unsigned*)&g_h[idx] = pk2h(__float2half_rn(o0), __float2half_rn(o1));
            }
        }
}

// ---- GEMM2: 128(M) x 128(N) x 32, warps 4(M) x 2(N), each warp 32Mx64N ----
#define G2_A    0
#define G2_B    5120
#define G2_STG  10240
#define G2_STGB (G2_STG * 2)
#define G2_SMEM (NSTG * G2_STGB)

__global__ __launch_bounds__(256, 2) void k_gemm2() {
    const int z  = blockIdx.z;
    const int m0 = blockIdx.y * 128;
    const int n0 = blockIdx.x * 128;
    const int M  = (z < NEXP) ? g_cnt[z] : TOK;
    if (m0 >= M) return;
    const size_t rowbase = (z < NEXP) ? ((size_t)z * TOK + m0) : ((size_t)ROWCAP + m0);

    extern __shared__ __align__(16) char sm[];
    const uint32_t sbu = smem_u32(sm);
    const int tid = threadIdx.x;
    const int ra = tid >> 2, c4 = tid & 3;

    const __half* sa0 = g_h + (rowbase + ra) * (size_t)FDIM + c4 * 8;
    const __half* sa1 = g_h + (rowbase + 64 + ra) * (size_t)FDIM + c4 * 8;
    const size_t bsrc = ((size_t)z * DDIM + n0 + ra) * FDIM + c4 * 8;
    const __half *sB0 = g_w2T + bsrc, *sB1 = sB0 + (size_t)64 * FDIM;

    const uint32_t dA0 = (G2_A + ra * LDT + c4 * 8) * 2;
    const uint32_t dA1 = dA0 + 64 * LDT * 2;
    const uint32_t dB0 = (G2_B + ra * LDT + c4 * 8) * 2;
    const uint32_t dB1 = dB0 + 64 * LDT * 2;

    const int lane = tid & 31, w = tid >> 5;
    const int wm = w >> 1, wn = w & 1;
    const int qr = lane >> 2, qc = lane & 3;
    const uint32_t aoff = ((wm * 32 + (lane & 15)) * LDT + (lane >> 4) * 8) * 2;
    const uint32_t boff = (G2_B + (wn * 64 + (lane & 7) + ((lane >> 4) & 1) * 8) * LDT
                           + ((lane >> 3) & 1) * 8) * 2;

    float acc[2][8][4] = {};

#define G2_LOAD(it) do { \
    const int k0 = (it) * 32; \
    const uint32_t db = sbu + ((it) % NSTG) * G2_STGB; \
    CP16(db + dA0, sa0 + k0); \
    CP16(db + dA1, sa1 + k0); \
    CP16(db + dB0, sB0 + k0); \
    CP16(db + dB1, sB1 + k0); \
    CPCOMMIT(); \
} while (0)

    G2_LOAD(0);
    G2_LOAD(1);
    G2_LOAD(2);

    const int NIT = FDIM / 32;
    for (int it = 0; it < NIT; it++) {
        CPWAIT2();
        __syncthreads();
        if (it + 3 < NIT) G2_LOAD(it + 3); else CPCOMMIT();
        const uint32_t stg = sbu + (it % NSTG) * G2_STGB;
#pragma unroll
        for (int ks = 0; ks < 32; ks += 16) {
            uint32_t ah[2][4];
#pragma unroll
            for (int mt = 0; mt < 2; mt++)
                ldsm4(ah[mt], stg + aoff + mt * (16 * LDT * 2) + ks * 2);
#pragma unroll
            for (int nh = 0; nh < 4; nh++) {
                uint32_t bb[4];
                ldsm4(bb, stg + boff + nh * (16 * LDT * 2) + ks * 2);
#pragma unroll
                for (int t = 0; t < 2; t++) {
                    const int nt = nh * 2 + t;
#pragma unroll
                    for (int mt = 0; mt < 2; mt++)
                        mma_f16(acc[mt][nt], ah[mt], bb + 2 * t);
                }
            }
        }
    }
#undef G2_LOAD

#pragma unroll
    for (int mt = 0; mt < 2; mt++)
#pragma unroll
        for (int nt = 0; nt < 8; nt++) {
            const int R = wm * 32 + mt * 16 + qr;
            const int C = n0 + wn * 64 + nt * 8 + 2 * qc;
#pragma unroll
            for (int half = 0; half < 2; half++) {
                const int r = R + half * 8;
                float2 o;
                o.x = acc[mt][nt][2 * half];
                o.y = acc[mt][nt][2 * half + 1];
                *(float2*)&g_orow[(rowbase + r) * (size_t)DDIM + C] = o;
            }
        }
}

// ============================ combine (float4) ===========================
__global__ void k_combine(float* __restrict__ out) {
    int idx = blockIdx.x * blockDim.x + threadIdx.x;   // one float4 per thread
    if (idx >= TOK * DDIM / 4) return;
    int t  = idx >> 8;                 // DDIM/4 = 256 vec4 per token
    int d4 = (idx & 255) * 4;
    float4 sh = *(const float4*)&g_orow[((size_t)ROWCAP + t) * DDIM + d4];
    int   r0 = g_rowof[2 * t], r1 = g_rowof[2 * t + 1];
    float g0 = g_gw[2 * t], g1 = g_gw[2 * t + 1];
    float4 a = *(const float4*)&g_orow[(size_t)r0 * DDIM + d4];
    float4 b = *(const float4*)&g_orow[(size_t)r1 * DDIM + d4];
    float4 o;
    o.x = 0.0625f * sh.x + 0.5f * (g0 * a.x + g1 * b.x);
    o.y = 0.0625f * sh.y + 0.5f * (g0 * a.y + g1 * b.y);
    o.z = 0.0625f * sh.z + 0.5f * (g0 * a.z + g1 * b.z);
    o.w = 0.0625f * sh.w + 0.5f * (g0 * a.w + g1 * b.w);
    *(float4*)&out[(size_t)t * DDIM + d4] = o;
}

// ============================ launch ====================================
extern "C" void kernel_launch(void* const* d_in, const int* in_sizes, int n_in,
                              void* d_out, int out_size) {
    const float* x   = (const float*)d_in[0];
    const float* gW  = (const float*)d_in[1];
    const float* w1e = (const float*)d_in[2];
    const float* w3e = (const float*)d_in[3];
    const float* w2e = (const float*)d_in[4];
    const float* w1s = (const float*)d_in[5];
    const float* w3s = (const float*)d_in[6];
    const float* w2s = (const float*)d_in[7];
    float* out = (float*)d_out;

    cudaFuncSetAttribute(k_gemm1, cudaFuncAttributeMaxDynamicSharedMemorySize, G1_SMEM);
    cudaFuncSetAttribute(k_gemm2, cudaFuncAttributeMaxDynamicSharedMemorySize, G2_SMEM);

    k_reset<<<1, 32>>>();
    k_gate<<<TOK / 8, 256>>>(x, gW);

    // routed: w1/w3 -> interleaved W' slots 0..7; w2 -> w2T slots 0..7
    // grids: x = source-cols/64 (output rows), y = source-rows/64 (K)
    k_transplit<<<dim3(FDIM / 64, DDIM / 64, NEXP), 256>>>(
        w1e, 0, 0, DDIM, FDIM, (size_t)DDIM * FDIM, (size_t)2 * FDIM * DDIM, 0);
    k_transplit<<<dim3(FDIM / 64, DDIM / 64, NEXP), 256>>>(
        w3e, 0, 0, DDIM, FDIM, (size_t)DDIM * FDIM, (size_t)2 * FDIM * DDIM, 32);
    k_transplit<<<dim3(DDIM / 64, FDIM / 64, NEXP), 256>>>(
        w2e, 1, 0, FDIM, DDIM, (size_t)FDIM * DDIM, (size_t)DDIM * FDIM, -1);
    // shared experts -> slot 8 (block-concatenated); per-z W' span = 1024 rows
    k_transplit<<<dim3(FSH / 64, DDIM / 64, NEXP), 256>>>(
        w1s, 0, (size_t)NEXP * 2 * FDIM * DDIM, DDIM, FSH, (size_t)DDIM * FSH,
        (size_t)1024 * DDIM, 0);
    k_transplit<<<dim3(FSH / 64, DDIM / 64, NEXP), 256>>>(
        w3s, 0, (size_t)NEXP * 2 * FDIM * DDIM, DDIM, FSH, (size_t)DDIM * FSH,
        (size_t)1024 * DDIM, 32);
    k_transplit<<<dim3(DDIM / 64, FDIM / 64, 1), 256>>>(
        w2s, 1, (size_t)NEXP * DDIM * FDIM, FDIM, DDIM, 0, 0, -1);

    k_gemm1<<<dim3(2 * FDIM / 128, TOK / 128, NSLOT), 256, G1_SMEM>>>();
    k_gemm2<<<dim3(DDIM / 128, TOK / 128, NSLOT), 256, G2_SMEM>>>();
    k_combine<<<(TOK * DDIM / 4) / 256, 256>>>(out);
}

// round 17
// speedup vs baseline: 1.4828x; 1.0522x over previous
#include <cuda_runtime.h>
#include <cuda_fp16.h>
#include <math.h>
#include <cstdint>
#include <string.h>

// ---------------- problem constants ----------------
#define TOK   2048
#define DDIM  1024
#define FDIM  4096
#define NEXP  8
#define FSH   512
#define TOPK  2
#define ROWCAP (NEXP*TOK)
#define NROWS  (ROWCAP + TOK)
#define NSLOT  9          // 8 routed + merged shared (slot 8)

// ---------------- scratch (device globals) ----------------
__device__ int   g_cnt[NEXP];
__device__ int   g_tok[ROWCAP];
__device__ int   g_rowof[TOK * TOPK];
__device__ float g_gw[TOK * TOPK];
__device__ __half g_x[TOK * DDIM];
// W' : per slot 2*FDIM rows (g/u interleaved in 32-row blocks), K-major [r'][D]
__device__ __half g_wgT[(size_t)NSLOT * 2 * FDIM * DDIM];
__device__ __half g_w2T[(size_t)NSLOT * DDIM * FDIM];   // [slot][D][F] fp16
__device__ __half g_h[(size_t)NROWS * FDIM];
__device__ float g_orow[(size_t)NROWS * DDIM];

// ---------------- helpers ----------------
__device__ __forceinline__ uint32_t smem_u32(const void* p) {
    uint32_t a;
    asm("{ .reg .u64 t; cvta.to.shared.u64 t, %1; cvt.u32.u64 %0, t; }" : "=r"(a) : "l"(p));
    return a;
}
__device__ __forceinline__ void ldsm4(uint32_t* r, uint32_t a) {
    asm volatile("ldmatrix.sync.aligned.m8n8.x4.shared.b16 {%0,%1,%2,%3}, [%4];"
                 : "=r"(r[0]), "=r"(r[1]), "=r"(r[2]), "=r"(r[3]) : "r"(a));
}
__device__ __forceinline__ void mma_f16(float* c, const uint32_t* a, const uint32_t* b) {
    asm volatile(
        "mma.sync.aligned.m16n8k16.row.col.f32.f16.f16.f32 "
        "{%0,%1,%2,%3},{%4,%5,%6,%7},{%8,%9},{%0,%1,%2,%3};"
        : "+f"(c[0]), "+f"(c[1]), "+f"(c[2]), "+f"(c[3])
        : "r"(a[0]), "r"(a[1]), "r"(a[2]), "r"(a[3]), "r"(b[0]), "r"(b[1]));
}
#define CP16(dst, src) \
    asm volatile("cp.async.cg.shared.global [%0], [%1], 16;" :: "r"(dst), "l"(src))
#define CPCOMMIT() asm volatile("cp.async.commit_group;" ::: "memory")
#define CPWAIT2()  asm volatile("cp.async.wait_group 2;" ::: "memory")

__device__ __forceinline__ unsigned pk2h(__half a, __half b) {
    __half2 t = __halves2half2(a, b);
    unsigned r; memcpy(&r, &t, 4); return r;
}

// ============================ reset / gate ===============================
__global__ void k_reset() {
    if (threadIdx.x < NEXP) g_cnt[threadIdx.x] = 0;
}

// gate + x fp16 conversion fused (warp already holds full row)
__global__ void k_gate(const float* __restrict__ x, const float* __restrict__ gateW) {
    int gwarp = (blockIdx.x * blockDim.x + threadIdx.x) >> 5;
    int lane  = threadIdx.x & 31;
    if (gwarp >= TOK) return;
    const float* xr = x + (size_t)gwarp * DDIM;
    float xv[32];
#pragma unroll
    for (int i = 0; i < 32; i++) xv[i] = xr[lane + 32 * i];

    __half* gx = g_x + (size_t)gwarp * DDIM + lane;
#pragma unroll
    for (int i = 0; i < 32; i++) gx[32 * i] = __float2half_rn(xv[i]);

    float logit[NEXP];
#pragma unroll
    for (int e = 0; e < NEXP; e++) {
        const float* wr = gateW + e * DDIM;
        float acc = 0.f;
#pragma unroll
        for (int i = 0; i < 32; i++) acc += xv[i] * wr[lane + 32 * i];
#pragma unroll
        for (int o = 16; o > 0; o >>= 1) acc += __shfl_xor_sync(0xffffffffu, acc, o);
        logit[e] = acc;
    }
    if (lane == 0) {
        float m = logit[0];
#pragma unroll
        for (int e = 1; e < NEXP; e++) m = fmaxf(m, logit[e]);
        float p[NEXP], den = 0.f;
#pragma unroll
        for (int e = 0; e < NEXP; e++) { p[e] = expf(logit[e] - m); den += p[e]; }
        int i1 = 0;
#pragma unroll
        for (int e = 1; e < NEXP; e++) if (p[e] > p[i1]) i1 = e;
        int i2 = (i1 == 0) ? 1 : 0;
#pragma unroll
        for (int e = 0; e < NEXP; e++) if (e != i2 && e != i1 && p[e] > p[i2]) i2 = e;
        int pos1 = atomicAdd(&g_cnt[i1], 1);
        int r1 = i1 * TOK + pos1;
        g_tok[r1] = gwarp;
        g_rowof[2 * gwarp + 0] = r1;
        g_gw[2 * gwarp + 0] = p[i1] / den;
        int pos2 = atomicAdd(&g_cnt[i2], 1);
        int r2 = i2 * TOK + pos2;
        g_tok[r2] = gwarp;
        g_rowof[2 * gwarp + 1] = r2;
        g_gw[2 * gwarp + 1] = p[i2] / den;
    }
}

// ===================== weight transpose (fp16) v3, GLU-merged ============
// zhalf > 0: z < zhalf -> src0 (goff 0), z >= zhalf -> src1 (goff 32),
// expert = z % zhalf. zhalf == 0: plain transpose of src0, slot z, goff -1.
// Tile: 64 K-rows x 64 source cols; 128B-contiguous half2 output stores.
__global__ __launch_bounds__(256) void k_transplit(
    const float* __restrict__ src0, const float* __restrict__ src1,
    int dst_id, size_t extra,
    int R, int C, size_t sstride, size_t dstride, int zhalf)
{
    __shared__ float tile[64][65];
    __half* dst = (dst_id == 0) ? g_wgT : g_w2T;
    dst += extra;

    const int z = blockIdx.z;
    int goff;
    const float* s;
    size_t dbase;
    if (zhalf > 0) {
        const int e = (z < zhalf) ? z : (z - zhalf);
        goff = (z < zhalf) ? 0 : 32;
        s = ((z < zhalf) ? src0 : src1) + (size_t)e * sstride;
        dbase = (size_t)e * dstride;
    } else {
        goff = -1;
        s = src0 + (size_t)z * sstride;
        dbase = (size_t)z * dstride;
    }

    int c0 = blockIdx.x * 64;    // output-row (source col) base
    int r0 = blockIdx.y * 64;    // K (source row) base
    const int tid = threadIdx.x;

#pragma unroll
    for (int i = 0; i < 16; i++) {
        int idx = tid + 256 * i;
        int k = idx >> 6, n = idx & 63;
        tile[k][n] = s[(size_t)(r0 + k) * C + c0 + n];
    }
    __syncthreads();

#pragma unroll
    for (int j = 0; j < 8; j++) {
        int n  = (tid >> 5) + 8 * j;
        int m2 = tid & 31;
        float v0 = tile[2 * m2][n];
        float v1 = tile[2 * m2 + 1][n];
        int r = c0 + n;
        int rr = (goff >= 0) ? (((r >> 5) << 6) + goff + (r & 31)) : r;
        __half2 hv = __halves2half2(__float2half_rn(v0), __float2half_rn(v1));
        *(__half2*)&dst[dbase + (size_t)rr * R + r0 + 2 * m2] = hv;
    }
}

// ============================ GEMM tiles ================================
#define LDT 40          // smem row stride in fp16 elems (80B, conflict-free ldmatrix)
#define NSTG 4
#define GN   4          // N-tiles per L2-reuse panel

// ---- GEMM1: 128(M) x 128(W'-rows) x 32, warps 4(M) x 2(N) ----
#define G1_A    0
#define G1_B    5120                  // 128 rows x LDT
#define G1_STG  10240                 // elems / stage
#define G1_STGB (G1_STG * 2)          // 20480 bytes / stage
#define G1_SMEM (NSTG * G1_STGB + 512)

__global__ __launch_bounds__(256, 2) void k_gemm1() {
    // L2-reuse swizzle: panels of GN N-tiles x all M-tiles
    const int lin = blockIdx.y * gridDim.x + blockIdx.x;
    const int PAN = GN * gridDim.y;
    const int bx  = (lin / PAN) * GN + (lin % GN);
    const int by  = (lin % PAN) / GN;

    const int z   = blockIdx.z;
    const int m0  = by * 128;
    const int n0p = bx * 128;             // W' row base
    const int M   = (z < NEXP) ? g_cnt[z] : TOK;
    if (m0 >= M) return;
    const size_t rowbase = (z < NEXP) ? ((size_t)z * TOK + m0) : ((size_t)ROWCAP + m0);

    extern __shared__ __align__(16) char sm[];
    int* stok = (int*)(sm + NSTG * G1_STGB);
    const int tid = threadIdx.x;
    if (tid < 128) {
        int r = m0 + tid; if (r > M - 1) r = M - 1;
        stok[tid] = (z < NEXP) ? g_tok[z * TOK + r] : r;
    }
    __syncthreads();

    const uint32_t sbu = smem_u32(sm);
    const int ra = tid >> 2, c4 = tid & 3;
    const int tA0 = stok[ra], tA1 = stok[64 + ra];
    const __half* sx0 = g_x + (size_t)tA0 * DDIM + c4 * 8;
    const __half* sx1 = g_x + (size_t)tA1 * DDIM + c4 * 8;
    const size_t bsrc = ((size_t)z * 2 * FDIM + n0p + ra) * DDIM + c4 * 8;
    const __half *sB0 = g_wgT + bsrc, *sB1 = sB0 + (size_t)64 * DDIM;

    const uint32_t dA0 = (G1_A + ra * LDT + c4 * 8) * 2;
    const uint32_t dA1 = dA0 + 64 * LDT * 2;
    const uint32_t dB0 = (G1_B + ra * LDT + c4 * 8) * 2;
    const uint32_t dB1 = dB0 + 64 * LDT * 2;

    const int lane = tid & 31, w = tid >> 5;
    const int wm = w >> 1, wn = w & 1;
    const int qr = lane >> 2, qc = lane & 3;
    const uint32_t aoff = ((wm * 32 + (lane & 15)) * LDT + (lane >> 4) * 8) * 2;
    const uint32_t boff = (G1_B + (wn * 64 + (lane & 7) + ((lane >> 4) & 1) * 8) * LDT
                           + ((lane >> 3) & 1) * 8) * 2;

    float acc[2][8][4] = {};

#define G1_LOAD(it) do { \
    const int k0 = (it) * 32; \
    const uint32_t db = sbu + ((it) % NSTG) * G1_STGB; \
    CP16(db + dA0, sx0 + k0); \
    CP16(db + dA1, sx1 + k0); \
    CP16(db + dB0, sB0 + k0); \
    CP16(db + dB1, sB1 + k0); \
    CPCOMMIT(); \
} while (0)

    G1_LOAD(0);
    G1_LOAD(1);
    G1_LOAD(2);

    const int NIT = DDIM / 32;
    for (int it = 0; it < NIT; it++) {
        CPWAIT2();
        __syncthreads();
        if (it + 3 < NIT) G1_LOAD(it + 3); else CPCOMMIT();
        const uint32_t stg = sbu + (it % NSTG) * G1_STGB;
#pragma unroll
        for (int ks = 0; ks < 32; ks += 16) {
            uint32_t ah[2][4];
#pragma unroll
            for (int mt = 0; mt < 2; mt++)
                ldsm4(ah[mt], stg + aoff + mt * (16 * LDT * 2) + ks * 2);
#pragma unroll
            for (int nh = 0; nh < 4; nh++) {
                uint32_t bb[4];
                ldsm4(bb, stg + boff + nh * (16 * LDT * 2) + ks * 2);
#pragma unroll
                for (int t = 0; t < 2; t++) {
                    const int nt = nh * 2 + t;
#pragma unroll
                    for (int mt = 0; mt < 2; mt++)
                        mma_f16(acc[mt][nt], ah[mt], bb + 2 * t);
                }
            }
        }
    }
#undef G1_LOAD

    // epilogue: GLU pairing in-register: g = acc[mt][nt], u = acc[mt][nt+4]
    const int fb = bx * 64 + wn * 32;
#pragma unroll
    for (int mt = 0; mt < 2; mt++)
#pragma unroll
        for (int nt = 0; nt < 4; nt++) {
            const int R = wm * 32 + mt * 16 + qr;
            const int C = fb + nt * 8 + 2 * qc;
#pragma unroll
            for (int half = 0; half < 2; half++) {
                const int r = R + half * 8;
                float g0 = acc[mt][nt][2 * half],     u0 = acc[mt][nt + 4][2 * half];
                float g1 = acc[mt][nt][2 * half + 1], u1 = acc[mt][nt + 4][2 * half + 1];
                float o0 = g0 / (1.f + __expf(-g0)) * u0;
                float o1 = g1 / (1.f + __expf(-g1)) * u1;
                const size_t idx = (rowbase + r) * (size_t)FDIM + C;
                *(unsigned*)&g_h[idx] = pk2h(__float2half_rn(o0), __float2half_rn(o1));
            }
        }
}

// ---- GEMM2: 128(M) x 128(N) x 32, warps 4(M) x 2(N), each warp 32Mx64N ----
#define G2_A    0
#define G2_B    5120
#define G2_STG  10240
#define G2_STGB (G2_STG * 2)
#define G2_SMEM (NSTG * G2_STGB)

__global__ __launch_bounds__(256, 2) void k_gemm2() {
    const int lin = blockIdx.y * gridDim.x + blockIdx.x;
    const int PAN = GN * gridDim.y;
    const int bx  = (lin / PAN) * GN + (lin % GN);
    const int by  = (lin % PAN) / GN;

    const int z  = blockIdx.z;
    const int m0 = by * 128;
    const int n0 = bx * 128;
    const int M  = (z < NEXP) ? g_cnt[z] : TOK;
    if (m0 >= M) return;
    const size_t rowbase = (z < NEXP) ? ((size_t)z * TOK + m0) : ((size_t)ROWCAP + m0);

    extern __shared__ __align__(16) char sm[];
    const uint32_t sbu = smem_u32(sm);
    const int tid = threadIdx.x;
    const int ra = tid >> 2, c4 = tid & 3;

    const __half* sa0 = g_h + (rowbase + ra) * (size_t)FDIM + c4 * 8;
    const __half* sa1 = g_h + (rowbase + 64 + ra) * (size_t)FDIM + c4 * 8;
    const size_t bsrc = ((size_t)z * DDIM + n0 + ra) * FDIM + c4 * 8;
    const __half *sB0 = g_w2T + bsrc, *sB1 = sB0 + (size_t)64 * FDIM;

    const uint32_t dA0 = (G2_A + ra * LDT + c4 * 8) * 2;
    const uint32_t dA1 = dA0 + 64 * LDT * 2;
    const uint32_t dB0 = (G2_B + ra * LDT + c4 * 8) * 2;
    const uint32_t dB1 = dB0 + 64 * LDT * 2;

    const int lane = tid & 31, w = tid >> 5;
    const int wm = w >> 1, wn = w & 1;
    const int qr = lane >> 2, qc = lane & 3;
    const uint32_t aoff = ((wm * 32 + (lane & 15)) * LDT + (lane >> 4) * 8) * 2;
    const uint32_t boff = (G2_B + (wn * 64 + (lane & 7) + ((lane >> 4) & 1) * 8) * LDT
                           + ((lane >> 3) & 1) * 8) * 2;

    float acc[2][8][4] = {};

#define G2_LOAD(it) do { \
    const int k0 = (it) * 32; \
    const uint32_t db = sbu + ((it) % NSTG) * G2_STGB; \
    CP16(db + dA0, sa0 + k0); \
    CP16(db + dA1, sa1 + k0); \
    CP16(db + dB0, sB0 + k0); \
    CP16(db + dB1, sB1 + k0); \
    CPCOMMIT(); \
} while (0)

    G2_LOAD(0);
    G2_LOAD(1);
    G2_LOAD(2);

    const int NIT = FDIM / 32;
    for (int it = 0; it < NIT; it++) {
        CPWAIT2();
        __syncthreads();
        if (it + 3 < NIT) G2_LOAD(it + 3); else CPCOMMIT();
        const uint32_t stg = sbu + (it % NSTG) * G2_STGB;
#pragma unroll
        for (int ks = 0; ks < 32; ks += 16) {
            uint32_t ah[2][4];
#pragma unroll
            for (int mt = 0; mt < 2; mt++)
                ldsm4(ah[mt], stg + aoff + mt * (16 * LDT * 2) + ks * 2);
#pragma unroll
            for (int nh = 0; nh < 4; nh++) {
                uint32_t bb[4];
                ldsm4(bb, stg + boff + nh * (16 * LDT * 2) + ks * 2);
#pragma unroll
                for (int t = 0; t < 2; t++) {
                    const int nt = nh * 2 + t;
#pragma unroll
                    for (int mt = 0; mt < 2; mt++)
                        mma_f16(acc[mt][nt], ah[mt], bb + 2 * t);
                }
            }
        }
    }
#undef G2_LOAD

#pragma unroll
    for (int mt = 0; mt < 2; mt++)
#pragma unroll
        for (int nt = 0; nt < 8; nt++) {
            const int R = wm * 32 + mt * 16 + qr;
            const int C = n0 + wn * 64 + nt * 8 + 2 * qc;
#pragma unroll
            for (int half = 0; half < 2; half++) {
                const int r = R + half * 8;
                float2 o;
                o.x = acc[mt][nt][2 * half];
                o.y = acc[mt][nt][2 * half + 1];
                *(float2*)&g_orow[(rowbase + r) * (size_t)DDIM + C] = o;
            }
        }
}

// ============================ combine (float4) ===========================
__global__ void k_combine(float* __restrict__ out) {
    int idx = blockIdx.x * blockDim.x + threadIdx.x;   // one float4 per thread
    if (idx >= TOK * DDIM / 4) return;
    int t  = idx >> 8;                 // DDIM/4 = 256 vec4 per token
    int d4 = (idx & 255) * 4;
    float4 sh = *(const float4*)&g_orow[((size_t)ROWCAP + t) * DDIM + d4];
    int   r0 = g_rowof[2 * t], r1 = g_rowof[2 * t + 1];
    float g0 = g_gw[2 * t], g1 = g_gw[2 * t + 1];
    float4 a = *(const float4*)&g_orow[(size_t)r0 * DDIM + d4];
    float4 b = *(const float4*)&g_orow[(size_t)r1 * DDIM + d4];
    float4 o;
    o.x = 0.0625f * sh.x + 0.5f * (g0 * a.x + g1 * b.x);
    o.y = 0.0625f * sh.y + 0.5f * (g0 * a.y + g1 * b.y);
    o.z = 0.0625f * sh.z + 0.5f * (g0 * a.z + g1 * b.z);
    o.w = 0.0625f * sh.w + 0.5f * (g0 * a.w + g1 * b.w);
    *(float4*)&out[(size_t)t * DDIM + d4] = o;
}

// ============================ launch ====================================
extern "C" void kernel_launch(void* const* d_in, const int* in_sizes, int n_in,
                              void* d_out, int out_size) {
    const float* x   = (const float*)d_in[0];
    const float* gW  = (const float*)d_in[1];
    const float* w1e = (const float*)d_in[2];
    const float* w3e = (const float*)d_in[3];
    const float* w2e = (const float*)d_in[4];
    const float* w1s = (const float*)d_in[5];
    const float* w3s = (const float*)d_in[6];
    const float* w2s = (const float*)d_in[7];
    float* out = (float*)d_out;

    cudaFuncSetAttribute(k_gemm1, cudaFuncAttributeMaxDynamicSharedMemorySize, G1_SMEM);
    cudaFuncSetAttribute(k_gemm2, cudaFuncAttributeMaxDynamicSharedMemorySize, G2_SMEM);

    // Launch order puts k_gemm1 at position 6 (ncu -s 5 -c 1 profiles it).
    k_reset<<<1, 32>>>();                                            // 1
    k_gate<<<TOK / 8, 256>>>(x, gW);                                 // 2

    // routed w1+w3 merged (z<8: w1 goff0, z>=8: w3 goff32)
    k_transplit<<<dim3(FDIM / 64, DDIM / 64, 2 * NEXP), 256>>>(      // 3
        w1e, w3e, 0, 0, DDIM, FDIM, (size_t)DDIM * FDIM,
        (size_t)2 * FDIM * DDIM, NEXP);
    // shared w1+w3 merged -> slot 8 (block-concatenated)
    k_transplit<<<dim3(FSH / 64, DDIM / 64, 2 * NEXP), 256>>>(       // 4
        w1s, w3s, 0, (size_t)NEXP * 2 * FDIM * DDIM, DDIM, FSH,
        (size_t)DDIM * FSH, (size_t)1024 * DDIM, NEXP);
    // routed w2
    k_transplit<<<dim3(DDIM / 64, FDIM / 64, NEXP), 256>>>(          // 5
        w2e, nullptr, 1, 0, FDIM, DDIM, (size_t)FDIM * DDIM,
        (size_t)DDIM * FDIM, 0);

    k_gemm1<<<dim3(2 * FDIM / 128, TOK / 128, NSLOT), 256, G1_SMEM>>>();  // 6 (profiled)

    // shared w2 -> slot 8 (needed only by gemm2; stream-ordered)
    k_transplit<<<dim3(DDIM / 64, FDIM / 64, 1), 256>>>(             // 7
        w2s, nullptr, 1, (size_t)NEXP * DDIM * FDIM, FDIM, DDIM, 0, 0, 0);

    k_gemm2<<<dim3(DDIM / 128, TOK / 128, NSLOT), 256, G2_SMEM>>>(); // 8
    k_combine<<<(TOK * DDIM / 4) / 256, 256>>>(out);                 // 9
}